// round 12
// baseline (speedup 1.0000x reference)
#include <cuda_runtime.h>
#include <cuda_bf16.h>
#include <cuda_fp16.h>
#include <cstdint>

// Problem constants
#define Bb 8
#define LL 1024
#define HH 8
#define EE 64
#define DD 64
#define SCALE 0.125f   // 1/sqrt(64)

// Output layout (concatenated flattened tuple):
//   V:      (B,L,H,D)   at 0              size 4,194,304
//   series: (B,H,L,S)   at 4,194,304      size 67,108,864
//   prior:  (B,L,S)     at 71,303,168     size 8,388,608
#define OFF_SERIES 4194304
#define OFF_PRIOR  71303168

// Scratch: per-(b,h,row,ntile) partial row sums of unnormalized exp scores.
__device__ float g_partial[Bb * HH * LL * 8];  // 2 MB

// ---------------- warp-MMA helpers (sm_80-era PTX, sm_103-portable) --------
struct U4 { uint32_t x, y, z, w; };

__device__ __forceinline__ U4 ldmx4(uint32_t a) {
    U4 r;
    asm volatile("ldmatrix.sync.aligned.m8n8.x4.shared.b16 {%0,%1,%2,%3}, [%4];"
                 : "=r"(r.x), "=r"(r.y), "=r"(r.z), "=r"(r.w) : "r"(a));
    return r;
}
__device__ __forceinline__ U4 ldmx4t(uint32_t a) {
    U4 r;
    asm volatile("ldmatrix.sync.aligned.m8n8.x4.trans.shared.b16 {%0,%1,%2,%3}, [%4];"
                 : "=r"(r.x), "=r"(r.y), "=r"(r.z), "=r"(r.w) : "r"(a));
    return r;
}
__device__ __forceinline__ void mma16816(float* c, const U4& a,
                                         uint32_t b0, uint32_t b1) {
    asm volatile("mma.sync.aligned.m16n8k16.row.col.f32.f16.f16.f32 "
                 "{%0,%1,%2,%3}, {%4,%5,%6,%7}, {%8,%9}, {%0,%1,%2,%3};"
                 : "+f"(c[0]), "+f"(c[1]), "+f"(c[2]), "+f"(c[3])
                 : "r"(a.x), "r"(a.y), "r"(a.z), "r"(a.w), "r"(b0), "r"(b1));
}
__device__ __forceinline__ uint32_t pack2h(half a, half b) {
    return (uint32_t)__half_as_ushort(a) | ((uint32_t)__half_as_ushort(b) << 16);
}
__device__ __forceinline__ uint32_t smem_u32(const void* p) {
    uint32_t a;
    asm("{ .reg .u64 t; cvta.to.shared.u64 t, %1; cvt.u32.u64 %0, t; }"
        : "=r"(a) : "l"(p));
    return a;
}
// SW128 swizzle (Swizzle<3,4,3>) on byte offsets within a 128B-row tile
__device__ __forceinline__ uint32_t sw128(uint32_t off) {
    return off ^ ((off >> 3) & 0x70);
}

// ===========================================================================
// Kernel A (k_sums): rowsums of E = exp(scale*QK^T), NO series stores.
// grid = (nt=8, mt=8, bh=64) with upper tiles returning immediately.
// ===========================================================================
#define SMQ_H 0
#define SMQ_L 16384
#define SMK_H 32768
#define SMK_L 49152
#define KS_SMEM 65536

__global__ __launch_bounds__(256, 2)
void k_sums(const float* __restrict__ Q, const float* __restrict__ K) {
    extern __shared__ __align__(1024) char dsm[];
    const int nt = blockIdx.x;
    const int mt = blockIdx.y;
    if (nt > mt) return;
    const int bh = blockIdx.z;          // b*8 + h
    const int b  = bh >> 3;
    const int h  = bh & 7;
    const int tid = threadIdx.x;

    const int row0 = mt * 128, col0 = nt * 128;

    __shared__ float rs[128][4];   // per-(row, warp_n) partial sums

    const uint32_t smb = smem_u32(dsm);
    const int wid = tid >> 5, lane = tid & 31;
    const int warp_m = wid & 1, warp_n = wid >> 1;
    const int m0 = warp_m * 64, n0w = warp_n * 32;
    const int g = lane >> 2, t = lane & 3;

    const float* Qg = Q + (size_t)b * LL * (HH * EE) + h * EE;
    const float* Kg = K + (size_t)b * LL * (HH * EE) + h * EE;
    #pragma unroll
    for (int it = 0; it < 8; it++) {
        int flat = it * 256 + tid;
        int c4 = flat & 15;
        int r  = flat >> 4;
        uint32_t so = sw128((uint32_t)(r * 128 + c4 * 8));

        float4 v = *(const float4*)(Qg + (size_t)(row0 + r) * 512 + c4 * 4);
        half hx = __float2half_rn(v.x), hy = __float2half_rn(v.y);
        half hz = __float2half_rn(v.z), hw = __float2half_rn(v.w);
        *(uint2*)(dsm + SMQ_H + so) = make_uint2(pack2h(hx, hy), pack2h(hz, hw));
        *(uint2*)(dsm + SMQ_L + so) = make_uint2(
            pack2h(__float2half_rn(v.x - __half2float(hx)),
                   __float2half_rn(v.y - __half2float(hy))),
            pack2h(__float2half_rn(v.z - __half2float(hz)),
                   __float2half_rn(v.w - __half2float(hw))));

        float4 w = *(const float4*)(Kg + (size_t)(col0 + r) * 512 + c4 * 4);
        half kx = __float2half_rn(w.x), ky = __float2half_rn(w.y);
        half kz = __float2half_rn(w.z), kw = __float2half_rn(w.w);
        *(uint2*)(dsm + SMK_H + so) = make_uint2(pack2h(kx, ky), pack2h(kz, kw));
        *(uint2*)(dsm + SMK_L + so) = make_uint2(
            pack2h(__float2half_rn(w.x - __half2float(kx)),
                   __float2half_rn(w.y - __half2float(ky))),
            pack2h(__float2half_rn(w.z - __half2float(kz)),
                   __float2half_rn(w.w - __half2float(kw))));
    }
    __syncthreads();

    const int a_row = (lane & 7) + ((lane >> 3) & 1) * 8;
    const int a_c16 = (lane >> 4) & 1;
    const int b_row = (lane & 7) + ((lane >> 4) & 1) * 8;
    const int b_c16 = (lane >> 3) & 1;

    uint32_t offA[4], offB[2];
    #pragma unroll
    for (int im = 0; im < 4; im++)
        offA[im] = (uint32_t)((m0 + im * 16 + a_row) * 128 + a_c16 * 16);
    #pragma unroll
    for (int hb = 0; hb < 2; hb++)
        offB[hb] = (uint32_t)((n0w + hb * 16 + b_row) * 128 + b_c16 * 16);

    float c[4][4][4];
    #pragma unroll
    for (int im = 0; im < 4; im++)
        #pragma unroll
        for (int in = 0; in < 4; in++)
            #pragma unroll
            for (int q = 0; q < 4; q++) c[im][in][q] = 0.f;

    #pragma unroll
    for (int ks = 0; ks < 4; ks++) {
        const uint32_t ko = ks * 32;
        U4 A[4], Bh[2], Bl[2];
        #pragma unroll
        for (int hb = 0; hb < 2; hb++)
            Bh[hb] = ldmx4(smb + SMK_H + sw128(offB[hb] + ko));
        #pragma unroll
        for (int im = 0; im < 4; im++)
            A[im] = ldmx4(smb + SMQ_H + sw128(offA[im] + ko));
        #pragma unroll
        for (int im = 0; im < 4; im++) {
            mma16816(c[im][0], A[im], Bh[0].x, Bh[0].y);
            mma16816(c[im][1], A[im], Bh[0].z, Bh[0].w);
            mma16816(c[im][2], A[im], Bh[1].x, Bh[1].y);
            mma16816(c[im][3], A[im], Bh[1].z, Bh[1].w);
        }
        #pragma unroll
        for (int hb = 0; hb < 2; hb++)
            Bl[hb] = ldmx4(smb + SMK_L + sw128(offB[hb] + ko));
        #pragma unroll
        for (int im = 0; im < 4; im++) {
            mma16816(c[im][0], A[im], Bl[0].x, Bl[0].y);
            mma16816(c[im][1], A[im], Bl[0].z, Bl[0].w);
            mma16816(c[im][2], A[im], Bl[1].x, Bl[1].y);
            mma16816(c[im][3], A[im], Bl[1].z, Bl[1].w);
        }
        #pragma unroll
        for (int im = 0; im < 4; im++)
            A[im] = ldmx4(smb + SMQ_L + sw128(offA[im] + ko));
        #pragma unroll
        for (int im = 0; im < 4; im++) {
            mma16816(c[im][0], A[im], Bh[0].x, Bh[0].y);
            mma16816(c[im][1], A[im], Bh[0].z, Bh[0].w);
            mma16816(c[im][2], A[im], Bh[1].x, Bh[1].y);
            mma16816(c[im][3], A[im], Bh[1].z, Bh[1].w);
        }
    }

    // ---- epilogue: mask + exp + rowsums only (no stores) ----
    #pragma unroll
    for (int im = 0; im < 4; im++) {
        const int lrA = m0 + im * 16 + g;
        const int lrB = lrA + 8;
        const int rowA = row0 + lrA, rowB = row0 + lrB;
        float sA = 0.f, sB = 0.f;
        #pragma unroll
        for (int in = 0; in < 4; in++) {
            const int cb = n0w + in * 8 + 2 * t;
            const int colX = col0 + cb, colY = colX + 1;
            sA += ((colX <= rowA) ? __expf(SCALE * c[im][in][0]) : 0.f)
                + ((colY <= rowA) ? __expf(SCALE * c[im][in][1]) : 0.f);
            sB += ((colX <= rowB) ? __expf(SCALE * c[im][in][2]) : 0.f)
                + ((colY <= rowB) ? __expf(SCALE * c[im][in][3]) : 0.f);
        }
        sA += __shfl_xor_sync(0xffffffffu, sA, 1);
        sA += __shfl_xor_sync(0xffffffffu, sA, 2);
        sB += __shfl_xor_sync(0xffffffffu, sB, 1);
        sB += __shfl_xor_sync(0xffffffffu, sB, 2);
        if (t == 0) { rs[lrA][warp_n] = sA; rs[lrB][warp_n] = sB; }
    }
    __syncthreads();

    if (tid < 128)
        g_partial[((size_t)bh * LL + row0 + tid) * 8 + nt] =
            rs[tid][0] + rs[tid][1] + rs[tid][2] + rs[tid][3];
}

// ===========================================================================
// Kernel B (k_fuse): recompute scores, write P = E*rinv directly (single
// series write), and O = P @ V via in-register C->A fragment reuse.
// grid = 512 linear (big mt first); warp = 16 rows x full s / 64 d.
// ===========================================================================
#define FB_QH 1024
#define FB_QL (FB_QH + 16384)
#define FB_KH (FB_QL + 16384)
#define FB_KL (FB_KH + 16384)
#define FB_VH (FB_KL + 16384)
#define FB_VL (FB_VH + 16384)
#define FB_SMEM (FB_VL + 16384)   // 99328 B

__global__ __launch_bounds__(256, 2)
void k_fuse(const float* __restrict__ Q, const float* __restrict__ K,
            const float* __restrict__ V, float* __restrict__ series,
            float* __restrict__ outV) {
    extern __shared__ __align__(1024) char fsm[];
    const int bx = blockIdx.x;
    const int mt = 7 - (bx >> 6);       // big tiles first
    const int bh = bx & 63;
    const int b  = bh >> 3;
    const int h  = bh & 7;
    const int tid = threadIdx.x;
    const int wid = tid >> 5, lane = tid & 31;
    const int m0 = wid * 16;
    const int g = lane >> 2, t = lane & 3;

    float* rinv = (float*)fsm;
    const uint32_t smb = smem_u32(fsm);

    float* S = series + (size_t)bh * LL * LL;
    const int row0 = mt * 128;
    const float* Qg = Q + (size_t)b * LL * 512 + h * 64;
    const float* Kg = K + (size_t)b * LL * 512 + h * 64;
    const float* Vg = V + (size_t)b * LL * 512 + h * 64;

    if (tid < 128) {
        float s = 0.f;
        for (int nt2 = 0; nt2 <= mt; nt2++)
            s += g_partial[((size_t)bh * LL + row0 + tid) * 8 + nt2];
        rinv[tid] = 1.0f / s;
    }

    // zero-fill upper tiles of this row block
    const float4 z4 = make_float4(0.f, 0.f, 0.f, 0.f);
    for (int ct = mt + 1; ct < 8; ct++) {
        const int cb = ct * 128;
        #pragma unroll
        for (int i = 0; i < 16; i++) {
            int flat = i * 256 + tid;
            int r = flat >> 5, cc = (flat & 31) << 2;
            *(float4*)(S + (size_t)(row0 + r) * LL + cb + cc) = z4;
        }
    }

    // stage Q hi/lo once
    #pragma unroll
    for (int it = 0; it < 8; it++) {
        int flat = it * 256 + tid;
        int c4 = flat & 15, r = flat >> 4;
        uint32_t so = sw128((uint32_t)(r * 128 + c4 * 8));
        float4 v = *(const float4*)(Qg + (size_t)(row0 + r) * 512 + c4 * 4);
        half hx = __float2half_rn(v.x), hy = __float2half_rn(v.y);
        half hz = __float2half_rn(v.z), hw = __float2half_rn(v.w);
        *(uint2*)(fsm + FB_QH + so) = make_uint2(pack2h(hx, hy), pack2h(hz, hw));
        *(uint2*)(fsm + FB_QL + so) = make_uint2(
            pack2h(__float2half_rn(v.x - __half2float(hx)),
                   __float2half_rn(v.y - __half2float(hy))),
            pack2h(__float2half_rn(v.z - __half2float(hz)),
                   __float2half_rn(v.w - __half2float(hw))));
    }
    __syncthreads();

    const float r0v = rinv[m0 + g];
    const float r1v = rinv[m0 + g + 8];
    const int rowA = row0 + m0 + g;
    const int rowB = rowA + 8;

    const int a_row = (lane & 7) + ((lane >> 3) & 1) * 8;
    const int a_c16 = (lane >> 4) & 1;
    const int b_row = (lane & 7) + ((lane >> 4) & 1) * 8;
    const int b_c16 = (lane >> 3) & 1;
    const int v_row = (lane & 7) + ((lane >> 3) & 1) * 8;
    const int v_n8  = (lane >> 4) & 1;
    const uint32_t offA = (uint32_t)((m0 + a_row) * 128 + a_c16 * 16);
    uint32_t offVb[4];
    #pragma unroll
    for (int dj = 0; dj < 4; dj++)
        offVb[dj] = (uint32_t)(v_row * 128 + dj * 32 + v_n8 * 16);

    float O[8][4];
    #pragma unroll
    for (int nb = 0; nb < 8; nb++)
        #pragma unroll
        for (int q = 0; q < 4; q++) O[nb][q] = 0.f;

    for (int nt = 0; nt <= mt; nt++) {
        __syncthreads();   // prev iteration's ldmatrix done before restage
        const int col0 = nt * 128;

        // stage K tile hi/lo
        #pragma unroll
        for (int it = 0; it < 8; it++) {
            int flat = it * 256 + tid;
            int c4 = flat & 15, r = flat >> 4;
            uint32_t so = sw128((uint32_t)(r * 128 + c4 * 8));
            float4 w = *(const float4*)(Kg + (size_t)(col0 + r) * 512 + c4 * 4);
            half kx = __float2half_rn(w.x), ky = __float2half_rn(w.y);
            half kz = __float2half_rn(w.z), kw = __float2half_rn(w.w);
            *(uint2*)(fsm + FB_KH + so) = make_uint2(pack2h(kx, ky), pack2h(kz, kw));
            *(uint2*)(fsm + FB_KL + so) = make_uint2(
                pack2h(__float2half_rn(w.x - __half2float(kx)),
                       __float2half_rn(w.y - __half2float(ky))),
                pack2h(__float2half_rn(w.z - __half2float(kz)),
                       __float2half_rn(w.w - __half2float(kw))));
        }
        // stage V chunk hi/lo (rows = s local, cols = d)
        #pragma unroll
        for (int it = 0; it < 8; it++) {
            int flat = it * 256 + tid;
            int c4 = flat & 15, s = flat >> 4;
            uint32_t so = sw128((uint32_t)(s * 128 + c4 * 8));
            float4 w = *(const float4*)(Vg + (size_t)(col0 + s) * 512 + c4 * 4);
            half vx = __float2half_rn(w.x), vy = __float2half_rn(w.y);
            half vz = __float2half_rn(w.z), vw = __float2half_rn(w.w);
            *(uint2*)(fsm + FB_VH + so) = make_uint2(pack2h(vx, vy), pack2h(vz, vw));
            *(uint2*)(fsm + FB_VL + so) = make_uint2(
                pack2h(__float2half_rn(w.x - __half2float(vx)),
                       __float2half_rn(w.y - __half2float(vy))),
                pack2h(__float2half_rn(w.z - __half2float(vz)),
                       __float2half_rn(w.w - __half2float(vw))));
        }
        __syncthreads();

        #pragma unroll
        for (int sl = 0; sl < 4; sl++) {
            const int sb = sl * 32;
            float c[4][4];
            #pragma unroll
            for (int j = 0; j < 4; j++)
                #pragma unroll
                for (int q = 0; q < 4; q++) c[j][q] = 0.f;

            // QK for this s32 slice
            #pragma unroll
            for (int ks = 0; ks < 4; ks++) {
                const uint32_t ko = ks * 32;
                const uint32_t ob0 = (uint32_t)((sb + b_row) * 128 + b_c16 * 16) + ko;
                const uint32_t ob1 = ob0 + 16 * 128;
                U4 B0 = ldmx4(smb + FB_KH + sw128(ob0));
                U4 B1 = ldmx4(smb + FB_KH + sw128(ob1));
                U4 Ah = ldmx4(smb + FB_QH + sw128(offA + ko));
                mma16816(c[0], Ah, B0.x, B0.y);
                mma16816(c[1], Ah, B0.z, B0.w);
                mma16816(c[2], Ah, B1.x, B1.y);
                mma16816(c[3], Ah, B1.z, B1.w);
                U4 C0 = ldmx4(smb + FB_KL + sw128(ob0));
                U4 C1 = ldmx4(smb + FB_KL + sw128(ob1));
                mma16816(c[0], Ah, C0.x, C0.y);
                mma16816(c[1], Ah, C0.z, C0.w);
                mma16816(c[2], Ah, C1.x, C1.y);
                mma16816(c[3], Ah, C1.z, C1.w);
                U4 Al = ldmx4(smb + FB_QL + sw128(offA + ko));
                mma16816(c[0], Al, B0.x, B0.y);
                mma16816(c[1], Al, B0.z, B0.w);
                mma16816(c[2], Al, B1.x, B1.y);
                mma16816(c[3], Al, B1.z, B1.w);
            }

            // epilogue: exp * rinv, store P, build fp16 hi/lo A-frags
            U4 Ph[2], Pl[2];
            #pragma unroll
            for (int j = 0; j < 4; j++) {
                const int colX = col0 + sb + j * 8 + 2 * t;
                float e0 = (colX     <= rowA) ? __expf(SCALE * c[j][0]) * r0v : 0.f;
                float e1 = (colX + 1 <= rowA) ? __expf(SCALE * c[j][1]) * r0v : 0.f;
                float e2 = (colX     <= rowB) ? __expf(SCALE * c[j][2]) * r1v : 0.f;
                float e3 = (colX + 1 <= rowB) ? __expf(SCALE * c[j][3]) * r1v : 0.f;
                *(float2*)(S + (size_t)rowA * LL + colX) = make_float2(e0, e1);
                *(float2*)(S + (size_t)rowB * LL + colX) = make_float2(e2, e3);
                half h0 = __float2half_rn(e0), h1 = __float2half_rn(e1);
                half h2 = __float2half_rn(e2), h3 = __float2half_rn(e3);
                uint32_t hi01 = pack2h(h0, h1), hi23 = pack2h(h2, h3);
                uint32_t lo01 = pack2h(__float2half_rn(e0 - __half2float(h0)),
                                       __float2half_rn(e1 - __half2float(h1)));
                uint32_t lo23 = pack2h(__float2half_rn(e2 - __half2float(h2)),
                                       __float2half_rn(e3 - __half2float(h3)));
                if (j & 1) {
                    Ph[j >> 1].z = hi01; Ph[j >> 1].w = hi23;
                    Pl[j >> 1].z = lo01; Pl[j >> 1].w = lo23;
                } else {
                    Ph[j >> 1].x = hi01; Ph[j >> 1].y = hi23;
                    Pl[j >> 1].x = lo01; Pl[j >> 1].y = lo23;
                }
            }

            // PV: O += P * V for this slice (2 s16 k-steps)
            #pragma unroll
            for (int jj = 0; jj < 2; jj++) {
                const uint32_t vr = (uint32_t)((sb + jj * 16) * 128);
                #pragma unroll
                for (int dj = 0; dj < 4; dj++) {
                    U4 Vh4 = ldmx4t(smb + FB_VH + sw128(offVb[dj] + vr));
                    U4 Vl4 = ldmx4t(smb + FB_VL + sw128(offVb[dj] + vr));
                    mma16816(O[2 * dj],     Ph[jj], Vh4.x, Vh4.y);
                    mma16816(O[2 * dj + 1], Ph[jj], Vh4.z, Vh4.w);
                    mma16816(O[2 * dj],     Pl[jj], Vh4.x, Vh4.y);
                    mma16816(O[2 * dj + 1], Pl[jj], Vh4.z, Vh4.w);
                    mma16816(O[2 * dj],     Ph[jj], Vl4.x, Vl4.y);
                    mma16816(O[2 * dj + 1], Ph[jj], Vl4.z, Vl4.w);
                }
            }
        }
    }

    // store O tile
    float* Og = outV + (size_t)b * LL * 512 + h * 64;
    #pragma unroll
    for (int nb = 0; nb < 8; nb++) {
        const int col = nb * 8 + 2 * t;
        *(float2*)(Og + (size_t)rowA * 512 + col) = make_float2(O[nb][0], O[nb][1]);
        *(float2*)(Og + (size_t)rowB * 512 + col) = make_float2(O[nb][2], O[nb][3]);
    }
}

// ---------------------------------------------------------------------------
// Kernel 3: prior association (MUFU-bound, ~20us; unchanged).
// ---------------------------------------------------------------------------
__global__ __launch_bounds__(256)
void k_prior(const float* __restrict__ sigma, float* __restrict__ prior) {
    const int b  = blockIdx.y;
    const int i0 = blockIdx.x * 32;
    const int tid = threadIdx.x;

    __shared__ float rl[8][1024];
    __shared__ float red[8];

    for (int idx = tid; idx < 8 * 1024; idx += 256) {
        int h = idx >> 10;
        int s = idx & 1023;
        rl[h][s] = -1.0f / sigma[((size_t)b * 8 + h) * 1024 + s];
    }
    __syncthreads();

    const int lane = tid & 31, wid = tid >> 5;

    for (int ii = 0; ii < 32; ii++) {
        const int i = i0 + ii;
        float p[4];
        float sum = 0.f;
        #pragma unroll
        for (int j = 0; j < 4; j++) {
            const int s = tid + j * 256;
            const float d = (float)((i > s) ? (i - s) : (s - i));
            float a = 0.f;
            #pragma unroll
            for (int h = 0; h < 8; h++)
                a += __expf(d * rl[h][s]);
            p[j] = a;
            sum += a;
        }
        #pragma unroll
        for (int off = 16; off; off >>= 1)
            sum += __shfl_xor_sync(0xffffffffu, sum, off);
        if (lane == 0) red[wid] = sum;
        __syncthreads();
        float tot = 0.f;
        #pragma unroll
        for (int w = 0; w < 8; w++) tot += red[w];
        const float inv = 1.0f / tot;
        float* dst = prior + (size_t)(b * 1024 + i) * 1024;
        #pragma unroll
        for (int j = 0; j < 4; j++)
            dst[tid + j * 256] = p[j] * inv;
        __syncthreads();
    }
}

// ---------------------------------------------------------------------------
extern "C" void kernel_launch(void* const* d_in, const int* in_sizes, int n_in,
                              void* d_out, int out_size) {
    (void)in_sizes; (void)n_in; (void)out_size;
    const float* Q   = (const float*)d_in[0];
    const float* K   = (const float*)d_in[1];
    const float* V   = (const float*)d_in[2];
    const float* sig = (const float*)d_in[3];
    float* out    = (float*)d_out;
    float* outV   = out;                 // (B,L,H,D)
    float* series = out + OFF_SERIES;    // (B,H,L,S)
    float* prior  = out + OFF_PRIOR;     // (B,L,S)

    cudaFuncSetAttribute(k_sums, cudaFuncAttributeMaxDynamicSharedMemorySize,
                         KS_SMEM);
    cudaFuncSetAttribute(k_fuse, cudaFuncAttributeMaxDynamicSharedMemorySize,
                         FB_SMEM);

    k_sums<<<dim3(8, 8, Bb * HH), 256, KS_SMEM>>>(Q, K);
    k_fuse<<<dim3(512, 1),       256, FB_SMEM>>>(Q, K, V, series, outV);
    k_prior<<<dim3(32, Bb),      256>>>(sig, prior);
}

// round 13
// speedup vs baseline: 1.0149x; 1.0149x over previous
#include <cuda_runtime.h>
#include <cuda_bf16.h>
#include <cuda_fp16.h>
#include <cstdint>

// Problem constants
#define Bb 8
#define LL 1024
#define HH 8
#define EE 64
#define DD 64
#define SCALE 0.125f   // 1/sqrt(64)

// Output layout (concatenated flattened tuple):
//   V:      (B,L,H,D)   at 0              size 4,194,304
//   series: (B,H,L,S)   at 4,194,304      size 67,108,864
//   prior:  (B,L,S)     at 71,303,168     size 8,388,608
#define OFF_SERIES 4194304
#define OFF_PRIOR  71303168

// Scratch: per-(b,h,row,ntile) partial row sums of unnormalized exp scores.
__device__ float g_partial[Bb * HH * LL * 8];  // 2 MB

// ---------------- warp-MMA helpers (sm_80-era PTX, sm_103-portable) --------
struct U4 { uint32_t x, y, z, w; };

__device__ __forceinline__ U4 ldmx4(uint32_t a) {
    U4 r;
    asm volatile("ldmatrix.sync.aligned.m8n8.x4.shared.b16 {%0,%1,%2,%3}, [%4];"
                 : "=r"(r.x), "=r"(r.y), "=r"(r.z), "=r"(r.w) : "r"(a));
    return r;
}
__device__ __forceinline__ U4 ldmx4t(uint32_t a) {
    U4 r;
    asm volatile("ldmatrix.sync.aligned.m8n8.x4.trans.shared.b16 {%0,%1,%2,%3}, [%4];"
                 : "=r"(r.x), "=r"(r.y), "=r"(r.z), "=r"(r.w) : "r"(a));
    return r;
}
__device__ __forceinline__ void mma16816(float* c, const U4& a,
                                         uint32_t b0, uint32_t b1) {
    asm volatile("mma.sync.aligned.m16n8k16.row.col.f32.f16.f16.f32 "
                 "{%0,%1,%2,%3}, {%4,%5,%6,%7}, {%8,%9}, {%0,%1,%2,%3};"
                 : "+f"(c[0]), "+f"(c[1]), "+f"(c[2]), "+f"(c[3])
                 : "r"(a.x), "r"(a.y), "r"(a.z), "r"(a.w), "r"(b0), "r"(b1));
}
__device__ __forceinline__ uint32_t pack2h(half a, half b) {
    return (uint32_t)__half_as_ushort(a) | ((uint32_t)__half_as_ushort(b) << 16);
}
__device__ __forceinline__ uint32_t smem_u32(const void* p) {
    uint32_t a;
    asm("{ .reg .u64 t; cvta.to.shared.u64 t, %1; cvt.u32.u64 %0, t; }"
        : "=r"(a) : "l"(p));
    return a;
}
// SW128 swizzle (128B rows)
__device__ __forceinline__ uint32_t sw128(uint32_t off) {
    return off ^ ((off >> 3) & 0x70);
}
// SW64 swizzle (64B rows)
__device__ __forceinline__ uint32_t sw64(uint32_t off) {
    return off ^ ((off >> 3) & 0x30);
}

// ===========================================================================
// Kernel A (k_sums): rowsums of E = exp(scale*QK^T), NO series stores.
// grid = (nt=8, mt=8, bh=64); upper tiles return immediately. (R12, proven)
// ===========================================================================
#define SMQ_H 0
#define SMQ_L 16384
#define SMK_H 32768
#define SMK_L 49152
#define KS_SMEM 65536

__global__ __launch_bounds__(256, 2)
void k_sums(const float* __restrict__ Q, const float* __restrict__ K) {
    extern __shared__ __align__(1024) char dsm[];
    const int nt = blockIdx.x;
    const int mt = blockIdx.y;
    if (nt > mt) return;
    const int bh = blockIdx.z;          // b*8 + h
    const int b  = bh >> 3;
    const int h  = bh & 7;
    const int tid = threadIdx.x;

    const int row0 = mt * 128, col0 = nt * 128;

    __shared__ float rs[128][4];

    const uint32_t smb = smem_u32(dsm);
    const int wid = tid >> 5, lane = tid & 31;
    const int warp_m = wid & 1, warp_n = wid >> 1;
    const int m0 = warp_m * 64, n0w = warp_n * 32;
    const int g = lane >> 2, t = lane & 3;

    const float* Qg = Q + (size_t)b * LL * (HH * EE) + h * EE;
    const float* Kg = K + (size_t)b * LL * (HH * EE) + h * EE;
    #pragma unroll
    for (int it = 0; it < 8; it++) {
        int flat = it * 256 + tid;
        int c4 = flat & 15;
        int r  = flat >> 4;
        uint32_t so = sw128((uint32_t)(r * 128 + c4 * 8));

        float4 v = *(const float4*)(Qg + (size_t)(row0 + r) * 512 + c4 * 4);
        half hx = __float2half_rn(v.x), hy = __float2half_rn(v.y);
        half hz = __float2half_rn(v.z), hw = __float2half_rn(v.w);
        *(uint2*)(dsm + SMQ_H + so) = make_uint2(pack2h(hx, hy), pack2h(hz, hw));
        *(uint2*)(dsm + SMQ_L + so) = make_uint2(
            pack2h(__float2half_rn(v.x - __half2float(hx)),
                   __float2half_rn(v.y - __half2float(hy))),
            pack2h(__float2half_rn(v.z - __half2float(hz)),
                   __float2half_rn(v.w - __half2float(hw))));

        float4 w = *(const float4*)(Kg + (size_t)(col0 + r) * 512 + c4 * 4);
        half kx = __float2half_rn(w.x), ky = __float2half_rn(w.y);
        half kz = __float2half_rn(w.z), kw = __float2half_rn(w.w);
        *(uint2*)(dsm + SMK_H + so) = make_uint2(pack2h(kx, ky), pack2h(kz, kw));
        *(uint2*)(dsm + SMK_L + so) = make_uint2(
            pack2h(__float2half_rn(w.x - __half2float(kx)),
                   __float2half_rn(w.y - __half2float(ky))),
            pack2h(__float2half_rn(w.z - __half2float(kz)),
                   __float2half_rn(w.w - __half2float(kw))));
    }
    __syncthreads();

    const int a_row = (lane & 7) + ((lane >> 3) & 1) * 8;
    const int a_c16 = (lane >> 4) & 1;
    const int b_row = (lane & 7) + ((lane >> 4) & 1) * 8;
    const int b_c16 = (lane >> 3) & 1;

    uint32_t offA[4], offB[2];
    #pragma unroll
    for (int im = 0; im < 4; im++)
        offA[im] = (uint32_t)((m0 + im * 16 + a_row) * 128 + a_c16 * 16);
    #pragma unroll
    for (int hb = 0; hb < 2; hb++)
        offB[hb] = (uint32_t)((n0w + hb * 16 + b_row) * 128 + b_c16 * 16);

    float c[4][4][4];
    #pragma unroll
    for (int im = 0; im < 4; im++)
        #pragma unroll
        for (int in = 0; in < 4; in++)
            #pragma unroll
            for (int q = 0; q < 4; q++) c[im][in][q] = 0.f;

    #pragma unroll
    for (int ks = 0; ks < 4; ks++) {
        const uint32_t ko = ks * 32;
        U4 A[4], Bh[2], Bl[2];
        #pragma unroll
        for (int hb = 0; hb < 2; hb++)
            Bh[hb] = ldmx4(smb + SMK_H + sw128(offB[hb] + ko));
        #pragma unroll
        for (int im = 0; im < 4; im++)
            A[im] = ldmx4(smb + SMQ_H + sw128(offA[im] + ko));
        #pragma unroll
        for (int im = 0; im < 4; im++) {
            mma16816(c[im][0], A[im], Bh[0].x, Bh[0].y);
            mma16816(c[im][1], A[im], Bh[0].z, Bh[0].w);
            mma16816(c[im][2], A[im], Bh[1].x, Bh[1].y);
            mma16816(c[im][3], A[im], Bh[1].z, Bh[1].w);
        }
        #pragma unroll
        for (int hb = 0; hb < 2; hb++)
            Bl[hb] = ldmx4(smb + SMK_L + sw128(offB[hb] + ko));
        #pragma unroll
        for (int im = 0; im < 4; im++) {
            mma16816(c[im][0], A[im], Bl[0].x, Bl[0].y);
            mma16816(c[im][1], A[im], Bl[0].z, Bl[0].w);
            mma16816(c[im][2], A[im], Bl[1].x, Bl[1].y);
            mma16816(c[im][3], A[im], Bl[1].z, Bl[1].w);
        }
        #pragma unroll
        for (int im = 0; im < 4; im++)
            A[im] = ldmx4(smb + SMQ_L + sw128(offA[im] + ko));
        #pragma unroll
        for (int im = 0; im < 4; im++) {
            mma16816(c[im][0], A[im], Bh[0].x, Bh[0].y);
            mma16816(c[im][1], A[im], Bh[0].z, Bh[0].w);
            mma16816(c[im][2], A[im], Bh[1].x, Bh[1].y);
            mma16816(c[im][3], A[im], Bh[1].z, Bh[1].w);
        }
    }

    #pragma unroll
    for (int im = 0; im < 4; im++) {
        const int lrA = m0 + im * 16 + g;
        const int lrB = lrA + 8;
        const int rowA = row0 + lrA, rowB = row0 + lrB;
        float sA = 0.f, sB = 0.f;
        #pragma unroll
        for (int in = 0; in < 4; in++) {
            const int cb = n0w + in * 8 + 2 * t;
            const int colX = col0 + cb, colY = colX + 1;
            sA += ((colX <= rowA) ? __expf(SCALE * c[im][in][0]) : 0.f)
                + ((colY <= rowA) ? __expf(SCALE * c[im][in][1]) : 0.f);
            sB += ((colX <= rowB) ? __expf(SCALE * c[im][in][2]) : 0.f)
                + ((colY <= rowB) ? __expf(SCALE * c[im][in][3]) : 0.f);
        }
        sA += __shfl_xor_sync(0xffffffffu, sA, 1);
        sA += __shfl_xor_sync(0xffffffffu, sA, 2);
        sB += __shfl_xor_sync(0xffffffffu, sB, 1);
        sB += __shfl_xor_sync(0xffffffffu, sB, 2);
        if (t == 0) { rs[lrA][warp_n] = sA; rs[lrB][warp_n] = sB; }
    }
    __syncthreads();

    if (tid < 128)
        g_partial[((size_t)bh * LL + row0 + tid) * 8 + nt] =
            rs[tid][0] + rs[tid][1] + rs[tid][2] + rs[tid][3];
}

// ===========================================================================
// Kernel B (k_pv): recompute QK per 32-s chunk, write P once to series,
// PV on HMMA. Reg-prefetch double-buffered K/V; single P smem buffer.
// grid = 512 linear (big mt first). 8 warps: warp_m 0-3 (32 m rows each);
// warp_n 0-1: splits s (16) for QK, splits d (32) for PV.
// ===========================================================================
#define PV_QH   1024
#define PV_QL   (PV_QH + 16384)       // Q hi/lo: 128x64 fp16, 16KB each
#define PV_PH   (PV_QL + 16384)       // P hi/lo: 128x32 fp16, 8KB each (SW64)
#define PV_PL   (PV_PH + 8192)
#define PV_BUF  (PV_PL + 8192)        // K/V double buffers, 16KB each:
#define PV_BSZ  16384                 //   KH +0 | KL +4096 | VH +8192 | VL +12288
#define PV_SMEM (PV_BUF + 2 * PV_BSZ) // 82944 B

__device__ __forceinline__ void pv_stage(const float4* ek, const float4* ev,
                                         char* __restrict__ buf, int tid) {
    #pragma unroll
    for (int it = 0; it < 2; it++) {
        int flat = it * 256 + tid;      // 512 float4 = 32 rows x 16
        int c4 = flat & 15;
        int r  = flat >> 4;
        uint32_t so = sw128((uint32_t)(r * 128 + c4 * 8));
        float4 w = ek[it];
        half kx = __float2half_rn(w.x), ky = __float2half_rn(w.y);
        half kz = __float2half_rn(w.z), kw = __float2half_rn(w.w);
        *(uint2*)(buf + so) = make_uint2(pack2h(kx, ky), pack2h(kz, kw));
        *(uint2*)(buf + 4096 + so) = make_uint2(
            pack2h(__float2half_rn(w.x - __half2float(kx)),
                   __float2half_rn(w.y - __half2float(ky))),
            pack2h(__float2half_rn(w.z - __half2float(kz)),
                   __float2half_rn(w.w - __half2float(kw))));
        float4 u = ev[it];
        half vx = __float2half_rn(u.x), vy = __float2half_rn(u.y);
        half vz = __float2half_rn(u.z), vw = __float2half_rn(u.w);
        *(uint2*)(buf + 8192 + so) = make_uint2(pack2h(vx, vy), pack2h(vz, vw));
        *(uint2*)(buf + 12288 + so) = make_uint2(
            pack2h(__float2half_rn(u.x - __half2float(vx)),
                   __float2half_rn(u.y - __half2float(vy))),
            pack2h(__float2half_rn(u.z - __half2float(vz)),
                   __float2half_rn(u.w - __half2float(vw))));
    }
}

__global__ __launch_bounds__(256, 2)
void k_pv(const float* __restrict__ Q, const float* __restrict__ K,
          const float* __restrict__ V, float* __restrict__ series,
          float* __restrict__ outV) {
    extern __shared__ __align__(1024) char psm[];
    const int bx = blockIdx.x;
    const int mt = 7 - (bx >> 6);       // big tiles first
    const int bh = bx & 63;
    const int b  = bh >> 3;
    const int h  = bh & 7;
    const int tid = threadIdx.x;
    const int wid = tid >> 5, lane = tid & 31;
    const int warp_m = wid & 3, warp_n = wid >> 2;
    const int m0 = warp_m * 32;
    const int n0 = warp_n * 32;         // d split for PV
    const int g = lane >> 2, t = lane & 3;

    float* rinv = (float*)psm;
    const uint32_t smb = smem_u32(psm);

    float* S = series + (size_t)bh * LL * LL;
    const int row0 = mt * 128;
    const float* Qg = Q + (size_t)b * LL * 512 + h * 64;
    const float* Kg = K + (size_t)b * LL * 512 + h * 64;
    const float* Vg = V + (size_t)b * LL * 512 + h * 64;

    if (tid < 128) {
        float s = 0.f;
        for (int nt2 = 0; nt2 <= mt; nt2++)
            s += g_partial[((size_t)bh * LL + row0 + tid) * 8 + nt2];
        rinv[tid] = 1.0f / s;
    }

    // zero-fill upper tiles of this row block (write-only, overlaps)
    const float4 z4 = make_float4(0.f, 0.f, 0.f, 0.f);
    for (int ct = mt + 1; ct < 8; ct++) {
        const int cb = ct * 128;
        #pragma unroll
        for (int i = 0; i < 16; i++) {
            int flat = i * 256 + tid;
            int r = flat >> 5, cc = (flat & 31) << 2;
            *(float4*)(S + (size_t)(row0 + r) * LL + cb + cc) = z4;
        }
    }

    // stage Q hi/lo once (128 x 64)
    #pragma unroll
    for (int it = 0; it < 8; it++) {
        int flat = it * 256 + tid;
        int c4 = flat & 15, r = flat >> 4;
        uint32_t so = sw128((uint32_t)(r * 128 + c4 * 8));
        float4 v = *(const float4*)(Qg + (size_t)(row0 + r) * 512 + c4 * 4);
        half hx = __float2half_rn(v.x), hy = __float2half_rn(v.y);
        half hz = __float2half_rn(v.z), hw = __float2half_rn(v.w);
        *(uint2*)(psm + PV_QH + so) = make_uint2(pack2h(hx, hy), pack2h(hz, hw));
        *(uint2*)(psm + PV_QL + so) = make_uint2(
            pack2h(__float2half_rn(v.x - __half2float(hx)),
                   __float2half_rn(v.y - __half2float(hy))),
            pack2h(__float2half_rn(v.z - __half2float(hz)),
                   __float2half_rn(v.w - __half2float(hw))));
    }

    // lane-address components
    const int a_row = (lane & 7) + ((lane >> 3) & 1) * 8;
    const int a_c16 = (lane >> 4) & 1;
    const int b_row = (lane & 7) + ((lane >> 4) & 1) * 8;
    const int b_c16 = (lane >> 3) & 1;
    const int v_row = (lane & 7) + ((lane >> 3) & 1) * 8;
    const int v_n8  = (lane >> 4) & 1;

    uint32_t offQA[2], offPA[2], offVb[2];
    #pragma unroll
    for (int im = 0; im < 2; im++) {
        offQA[im] = (uint32_t)((m0 + im * 16 + a_row) * 128 + a_c16 * 16);
        offPA[im] = (uint32_t)((m0 + im * 16 + a_row) * 64 + a_c16 * 16);
    }
    #pragma unroll
    for (int in16 = 0; in16 < 2; in16++)
        offVb[in16] = (uint32_t)(v_row * 128 + n0 * 2 + in16 * 32 + v_n8 * 16);
    const uint32_t offKB = (uint32_t)((warp_n * 16 + b_row) * 128 + b_c16 * 16);

    // rinv per owned row
    __syncthreads();
    float rA[2], rB[2];
    #pragma unroll
    for (int im = 0; im < 2; im++) {
        rA[im] = rinv[m0 + im * 16 + g];
        rB[im] = rinv[m0 + im * 16 + g + 8];
    }

    float O[2][4][4];
    #pragma unroll
    for (int im = 0; im < 2; im++)
        #pragma unroll
        for (int jn = 0; jn < 4; jn++)
            #pragma unroll
            for (int q = 0; q < 4; q++) O[im][jn][q] = 0.f;

    const int nchunks = 4 * (mt + 1);   // 32-s chunks
    float4 ek[2], ev[2];

    {   // prolog: prefetch + stage chunk 0 into buf 0
        const int s0 = mt * 128;
        #pragma unroll
        for (int it = 0; it < 2; it++) {
            int flat = it * 256 + tid;
            int c4 = flat & 15, r = flat >> 4;
            ek[it] = *(const float4*)(Kg + (size_t)(s0 + r) * 512 + c4 * 4);
            ev[it] = *(const float4*)(Vg + (size_t)(s0 + r) * 512 + c4 * 4);
        }
        pv_stage(ek, ev, psm + PV_BUF, tid);
    }
    __syncthreads();

    for (int cc = 0; cc < nchunks; cc++) {
        const int buf = cc & 1;
        const bool more = (cc + 1 < nchunks);
        const int s0 = (mt - (cc >> 2)) * 128 + (cc & 3) * 32;

        if (more) {
            const int cn = cc + 1;
            const int s0n = (mt - (cn >> 2)) * 128 + (cn & 3) * 32;
            #pragma unroll
            for (int it = 0; it < 2; it++) {
                int flat = it * 256 + tid;
                int c4 = flat & 15, r = flat >> 4;
                ek[it] = *(const float4*)(Kg + (size_t)(s0n + r) * 512 + c4 * 4);
                ev[it] = *(const float4*)(Vg + (size_t)(s0n + r) * 512 + c4 * 4);
            }
        }

        // ---- QK for this chunk: warp tile 32m x 16s ----
        const uint32_t kbase = smb + PV_BUF + buf * PV_BSZ;
        float c[2][2][4];
        #pragma unroll
        for (int im = 0; im < 2; im++)
            #pragma unroll
            for (int j = 0; j < 2; j++)
                #pragma unroll
                for (int q = 0; q < 4; q++) c[im][j][q] = 0.f;

        #pragma unroll
        for (int ks = 0; ks < 4; ks++) {
            const uint32_t ko = ks * 32;
            U4 Bh = ldmx4(kbase + sw128(offKB + ko));
            U4 Ah0 = ldmx4(smb + PV_QH + sw128(offQA[0] + ko));
            U4 Ah1 = ldmx4(smb + PV_QH + sw128(offQA[1] + ko));
            mma16816(c[0][0], Ah0, Bh.x, Bh.y);
            mma16816(c[0][1], Ah0, Bh.z, Bh.w);
            mma16816(c[1][0], Ah1, Bh.x, Bh.y);
            mma16816(c[1][1], Ah1, Bh.z, Bh.w);
            U4 Bl = ldmx4(kbase + 4096 + sw128(offKB + ko));
            mma16816(c[0][0], Ah0, Bl.x, Bl.y);
            mma16816(c[0][1], Ah0, Bl.z, Bl.w);
            mma16816(c[1][0], Ah1, Bl.x, Bl.y);
            mma16816(c[1][1], Ah1, Bl.z, Bl.w);
            U4 Al0 = ldmx4(smb + PV_QL + sw128(offQA[0] + ko));
            U4 Al1 = ldmx4(smb + PV_QL + sw128(offQA[1] + ko));
            mma16816(c[0][0], Al0, Bh.x, Bh.y);
            mma16816(c[0][1], Al0, Bh.z, Bh.w);
            mma16816(c[1][0], Al1, Bh.x, Bh.y);
            mma16816(c[1][1], Al1, Bh.z, Bh.w);
        }

        // ---- epilogue: P = exp*rinv; store to series; stage Ph/Pl (SW64) ----
        #pragma unroll
        for (int im = 0; im < 2; im++) {
            const int rowA = row0 + m0 + im * 16 + g;
            const int rowB = rowA + 8;
            #pragma unroll
            for (int j = 0; j < 2; j++) {
                const int scol = warp_n * 16 + j * 8 + 2 * t;   // 0..31
                const int colX = s0 + scol;
                float e0 = (colX     <= rowA) ? __expf(SCALE * c[im][j][0]) * rA[im] : 0.f;
                float e1 = (colX + 1 <= rowA) ? __expf(SCALE * c[im][j][1]) * rA[im] : 0.f;
                float e2 = (colX     <= rowB) ? __expf(SCALE * c[im][j][2]) * rB[im] : 0.f;
                float e3 = (colX + 1 <= rowB) ? __expf(SCALE * c[im][j][3]) * rB[im] : 0.f;
                *(float2*)(S + (size_t)rowA * LL + colX) = make_float2(e0, e1);
                *(float2*)(S + (size_t)rowB * LL + colX) = make_float2(e2, e3);
                half h0 = __float2half_rn(e0), h1 = __float2half_rn(e1);
                half h2 = __float2half_rn(e2), h3 = __float2half_rn(e3);
                uint32_t oA = sw64((uint32_t)((m0 + im * 16 + g) * 64 + scol * 2));
                uint32_t oB = sw64((uint32_t)((m0 + im * 16 + g + 8) * 64 + scol * 2));
                *(uint32_t*)(psm + PV_PH + oA) = pack2h(h0, h1);
                *(uint32_t*)(psm + PV_PH + oB) = pack2h(h2, h3);
                *(uint32_t*)(psm + PV_PL + oA) =
                    pack2h(__float2half_rn(e0 - __half2float(h0)),
                           __float2half_rn(e1 - __half2float(h1)));
                *(uint32_t*)(psm + PV_PL + oB) =
                    pack2h(__float2half_rn(e2 - __half2float(h2)),
                           __float2half_rn(e3 - __half2float(h3)));
            }
        }
        __syncthreads();   // P visible; K/V buf reads (QK) complete

        // ---- PV: O += P * V over this chunk (2 s16 steps) ----
        #pragma unroll
        for (int sk = 0; sk < 2; sk++) {
            const uint32_t po = sk * 32;
            const uint32_t vr = sk * 2048;
            U4 Ph0 = ldmx4(smb + PV_PH + sw64(offPA[0] + po));
            U4 Ph1 = ldmx4(smb + PV_PH + sw64(offPA[1] + po));
            U4 Pl0 = ldmx4(smb + PV_PL + sw64(offPA[0] + po));
            U4 Pl1 = ldmx4(smb + PV_PL + sw64(offPA[1] + po));
            #pragma unroll
            for (int in16 = 0; in16 < 2; in16++) {
                U4 Vh4 = ldmx4t(kbase + 8192 + sw128(offVb[in16] + vr));
                U4 Vl4 = ldmx4t(kbase + 12288 + sw128(offVb[in16] + vr));
                mma16816(O[0][2 * in16],     Ph0, Vh4.x, Vh4.y);
                mma16816(O[0][2 * in16 + 1], Ph0, Vh4.z, Vh4.w);
                mma16816(O[1][2 * in16],     Ph1, Vh4.x, Vh4.y);
                mma16816(O[1][2 * in16 + 1], Ph1, Vh4.z, Vh4.w);
                mma16816(O[0][2 * in16],     Pl0, Vh4.x, Vh4.y);
                mma16816(O[0][2 * in16 + 1], Pl0, Vh4.z, Vh4.w);
                mma16816(O[1][2 * in16],     Pl1, Vh4.x, Vh4.y);
                mma16816(O[1][2 * in16 + 1], Pl1, Vh4.z, Vh4.w);
                mma16816(O[0][2 * in16],     Ph0, Vl4.x, Vl4.y);
                mma16816(O[0][2 * in16 + 1], Ph0, Vl4.z, Vl4.w);
                mma16816(O[1][2 * in16],     Ph1, Vl4.x, Vl4.y);
                mma16816(O[1][2 * in16 + 1], Ph1, Vl4.z, Vl4.w);
            }
        }

        if (more)
            pv_stage(ek, ev, psm + PV_BUF + (buf ^ 1) * PV_BSZ, tid);
        __syncthreads();   // staging visible; PV done before next P overwrite
    }

    // ---- store O tile (warp owns 32m x 32d) ----
    float* Og = outV + (size_t)b * LL * 512 + h * 64;
    #pragma unroll
    for (int im = 0; im < 2; im++) {
        const int rowA = row0 + m0 + im * 16 + g;
        const int rowB = rowA + 8;
        #pragma unroll
        for (int jn = 0; jn < 4; jn++) {
            const int col = n0 + jn * 8 + 2 * t;
            *(float2*)(Og + (size_t)rowA * 512 + col) =
                make_float2(O[im][jn][0], O[im][jn][1]);
            *(float2*)(Og + (size_t)rowB * 512 + col) =
                make_float2(O[im][jn][2], O[im][jn][3]);
        }
    }
}

// ---------------------------------------------------------------------------
// Kernel 3: prior association (MUFU-bound, ~20us; unchanged).
// ---------------------------------------------------------------------------
__global__ __launch_bounds__(256)
void k_prior(const float* __restrict__ sigma, float* __restrict__ prior) {
    const int b  = blockIdx.y;
    const int i0 = blockIdx.x * 32;
    const int tid = threadIdx.x;

    __shared__ float rl[8][1024];
    __shared__ float red[8];

    for (int idx = tid; idx < 8 * 1024; idx += 256) {
        int h = idx >> 10;
        int s = idx & 1023;
        rl[h][s] = -1.0f / sigma[((size_t)b * 8 + h) * 1024 + s];
    }
    __syncthreads();

    const int lane = tid & 31, wid = tid >> 5;

    for (int ii = 0; ii < 32; ii++) {
        const int i = i0 + ii;
        float p[4];
        float sum = 0.f;
        #pragma unroll
        for (int j = 0; j < 4; j++) {
            const int s = tid + j * 256;
            const float d = (float)((i > s) ? (i - s) : (s - i));
            float a = 0.f;
            #pragma unroll
            for (int h = 0; h < 8; h++)
                a += __expf(d * rl[h][s]);
            p[j] = a;
            sum += a;
        }
        #pragma unroll
        for (int off = 16; off; off >>= 1)
            sum += __shfl_xor_sync(0xffffffffu, sum, off);
        if (lane == 0) red[wid] = sum;
        __syncthreads();
        float tot = 0.f;
        #pragma unroll
        for (int w = 0; w < 8; w++) tot += red[w];
        const float inv = 1.0f / tot;
        float* dst = prior + (size_t)(b * 1024 + i) * 1024;
        #pragma unroll
        for (int j = 0; j < 4; j++)
            dst[tid + j * 256] = p[j] * inv;
        __syncthreads();
    }
}

// ---------------------------------------------------------------------------
extern "C" void kernel_launch(void* const* d_in, const int* in_sizes, int n_in,
                              void* d_out, int out_size) {
    (void)in_sizes; (void)n_in; (void)out_size;
    const float* Q   = (const float*)d_in[0];
    const float* K   = (const float*)d_in[1];
    const float* V   = (const float*)d_in[2];
    const float* sig = (const float*)d_in[3];
    float* out    = (float*)d_out;
    float* outV   = out;                 // (B,L,H,D)
    float* series = out + OFF_SERIES;    // (B,H,L,S)
    float* prior  = out + OFF_PRIOR;     // (B,L,S)

    cudaFuncSetAttribute(k_sums, cudaFuncAttributeMaxDynamicSharedMemorySize,
                         KS_SMEM);
    cudaFuncSetAttribute(k_pv, cudaFuncAttributeMaxDynamicSharedMemorySize,
                         PV_SMEM);

    k_sums<<<dim3(8, 8, Bb * HH), 256, KS_SMEM>>>(Q, K);
    k_pv  <<<dim3(512, 1),       256, PV_SMEM>>>(Q, K, V, series, outV);
    k_prior<<<dim3(32, Bb),      256>>>(sig, prior);
}

// round 14
// speedup vs baseline: 1.1913x; 1.1738x over previous
#include <cuda_runtime.h>
#include <cuda_bf16.h>
#include <cuda_fp16.h>
#include <cstdint>

// Problem constants
#define Bb 8
#define LL 1024
#define HH 8
#define EE 64
#define DD 64
#define SCALE 0.125f   // 1/sqrt(64)

// Output layout (concatenated flattened tuple):
//   V:      (B,L,H,D)   at 0              size 4,194,304
//   series: (B,H,L,S)   at 4,194,304      size 67,108,864
//   prior:  (B,L,S)     at 71,303,168     size 8,388,608
#define OFF_SERIES 4194304
#define OFF_PRIOR  71303168

// Scratch: per-(b,h,row,ntile) partial row sums of unnormalized exp scores.
__device__ float g_partial[Bb * HH * LL * 8];  // 2 MB

// ---------------- warp-MMA helpers (sm_80-era PTX, sm_103-portable) --------
struct U4 { uint32_t x, y, z, w; };

__device__ __forceinline__ U4 ldmx4(uint32_t a) {
    U4 r;
    asm volatile("ldmatrix.sync.aligned.m8n8.x4.shared.b16 {%0,%1,%2,%3}, [%4];"
                 : "=r"(r.x), "=r"(r.y), "=r"(r.z), "=r"(r.w) : "r"(a));
    return r;
}
__device__ __forceinline__ U4 ldmx4t(uint32_t a) {
    U4 r;
    asm volatile("ldmatrix.sync.aligned.m8n8.x4.trans.shared.b16 {%0,%1,%2,%3}, [%4];"
                 : "=r"(r.x), "=r"(r.y), "=r"(r.z), "=r"(r.w) : "r"(a));
    return r;
}
__device__ __forceinline__ void mma16816(float* c, const U4& a,
                                         uint32_t b0, uint32_t b1) {
    asm volatile("mma.sync.aligned.m16n8k16.row.col.f32.f16.f16.f32 "
                 "{%0,%1,%2,%3}, {%4,%5,%6,%7}, {%8,%9}, {%0,%1,%2,%3};"
                 : "+f"(c[0]), "+f"(c[1]), "+f"(c[2]), "+f"(c[3])
                 : "r"(a.x), "r"(a.y), "r"(a.z), "r"(a.w), "r"(b0), "r"(b1));
}
__device__ __forceinline__ uint32_t pack2h(half a, half b) {
    return (uint32_t)__half_as_ushort(a) | ((uint32_t)__half_as_ushort(b) << 16);
}
__device__ __forceinline__ uint32_t smem_u32(const void* p) {
    uint32_t a;
    asm("{ .reg .u64 t; cvta.to.shared.u64 t, %1; cvt.u32.u64 %0, t; }"
        : "=r"(a) : "l"(p));
    return a;
}
// SW128 swizzle (Swizzle<3,4,3>) on byte offsets within a 128B-row tile
__device__ __forceinline__ uint32_t sw128(uint32_t off) {
    return off ^ ((off >> 3) & 0x70);
}

// ===========================================================================
// Kernel 1 (HMMA + fused prior): grid (8, 8, 64+4).
//   z < 64 : E = exp(scale * Q K^T) causal tile (R11 path, direct stores)
//   z >= 64: prior-association blocks (MUFU-bound; overlaps with scores)
// ===========================================================================
#define SMQ_H 0
#define SMQ_L 16384
#define SMK_H 32768
#define SMK_L 49152
#define KS_SMEM 65536

__global__ __launch_bounds__(256, 2)
void k_scores(const float* __restrict__ Q, const float* __restrict__ K,
              float* __restrict__ series,
              const float* __restrict__ sigma, float* __restrict__ prior) {
    extern __shared__ __align__(1024) char dsm[];
    const int tid = threadIdx.x;

    // ---------------- prior path (z = 64..67) ----------------
    if (blockIdx.z >= 64) {
        const int flat = (blockIdx.z - 64) * 64 + blockIdx.y * 8 + blockIdx.x;
        const int i0 = (flat >> 3) * 32;
        const int b  = flat & 7;
        float* rl  = (float*)dsm;              // [8][1024]
        float* red = (float*)(dsm + 32768);    // [8]

        for (int idx = tid; idx < 8 * 1024; idx += 256) {
            int hh = idx >> 10;
            int s  = idx & 1023;
            rl[hh * 1024 + s] = -1.0f / sigma[((size_t)b * 8 + hh) * 1024 + s];
        }
        __syncthreads();

        const int lane = tid & 31, wd = tid >> 5;
        for (int ii = 0; ii < 32; ii++) {
            const int i = i0 + ii;
            float p[4];
            float sum = 0.f;
            #pragma unroll
            for (int j = 0; j < 4; j++) {
                const int s = tid + j * 256;
                const float d = (float)((i > s) ? (i - s) : (s - i));
                float a = 0.f;
                #pragma unroll
                for (int hh = 0; hh < 8; hh++)
                    a += __expf(d * rl[hh * 1024 + s]);
                p[j] = a;
                sum += a;
            }
            #pragma unroll
            for (int off = 16; off; off >>= 1)
                sum += __shfl_xor_sync(0xffffffffu, sum, off);
            if (lane == 0) red[wd] = sum;
            __syncthreads();
            float tot = 0.f;
            #pragma unroll
            for (int w = 0; w < 8; w++) tot += red[w];
            const float inv = 1.0f / tot;
            float* dst = prior + (size_t)(b * 1024 + i) * 1024;
            #pragma unroll
            for (int j = 0; j < 4; j++)
                dst[tid + j * 256] = p[j] * inv;
            __syncthreads();
        }
        return;
    }

    // ---------------- scores path (z = 0..63) ----------------
    const int nt = blockIdx.x;
    const int mt = blockIdx.y;
    const int bh = blockIdx.z;          // b*8 + h
    const int b  = bh >> 3;
    const int h  = bh & 7;

    float* S = series + (size_t)bh * LL * LL;
    const int row0 = mt * 128, col0 = nt * 128;

    if (nt > mt) {
        const float4 z = make_float4(0.f, 0.f, 0.f, 0.f);
        #pragma unroll
        for (int i = 0; i < 16; i++) {
            int flat = i * 256 + tid;
            int r = flat >> 5;
            int c = (flat & 31) << 2;
            *(float4*)(S + (size_t)(row0 + r) * LL + col0 + c) = z;
        }
        return;
    }

    __shared__ float rs[128][4];   // per-(row, warp_n) partial sums

    const uint32_t smb = smem_u32(dsm);
    const int wid = tid >> 5, lane = tid & 31;
    const int warp_m = wid & 1, warp_n = wid >> 1;
    const int m0 = warp_m * 64, n0w = warp_n * 32;
    const int g = lane >> 2, t = lane & 3;

    const float* Qg = Q + (size_t)b * LL * (HH * EE) + h * EE;  // + l*512 + e
    const float* Kg = K + (size_t)b * LL * (HH * EE) + h * EE;
    #pragma unroll
    for (int it = 0; it < 8; it++) {
        int flat = it * 256 + tid;      // 2048 float4 per matrix
        int c4 = flat & 15;
        int r  = flat >> 4;
        uint32_t so = sw128((uint32_t)(r * 128 + c4 * 8));

        float4 v = *(const float4*)(Qg + (size_t)(row0 + r) * 512 + c4 * 4);
        half hx = __float2half_rn(v.x), hy = __float2half_rn(v.y);
        half hz = __float2half_rn(v.z), hw = __float2half_rn(v.w);
        *(uint2*)(dsm + SMQ_H + so) = make_uint2(pack2h(hx, hy), pack2h(hz, hw));
        *(uint2*)(dsm + SMQ_L + so) = make_uint2(
            pack2h(__float2half_rn(v.x - __half2float(hx)),
                   __float2half_rn(v.y - __half2float(hy))),
            pack2h(__float2half_rn(v.z - __half2float(hz)),
                   __float2half_rn(v.w - __half2float(hw))));

        float4 w = *(const float4*)(Kg + (size_t)(col0 + r) * 512 + c4 * 4);
        half kx = __float2half_rn(w.x), ky = __float2half_rn(w.y);
        half kz = __float2half_rn(w.z), kw = __float2half_rn(w.w);
        *(uint2*)(dsm + SMK_H + so) = make_uint2(pack2h(kx, ky), pack2h(kz, kw));
        *(uint2*)(dsm + SMK_L + so) = make_uint2(
            pack2h(__float2half_rn(w.x - __half2float(kx)),
                   __float2half_rn(w.y - __half2float(ky))),
            pack2h(__float2half_rn(w.z - __half2float(kz)),
                   __float2half_rn(w.w - __half2float(kw))));
    }
    __syncthreads();

    const int a_row = (lane & 7) + ((lane >> 3) & 1) * 8;
    const int a_c16 = (lane >> 4) & 1;
    const int b_row = (lane & 7) + ((lane >> 4) & 1) * 8;
    const int b_c16 = (lane >> 3) & 1;

    uint32_t offA[4], offB[2];
    #pragma unroll
    for (int im = 0; im < 4; im++)
        offA[im] = (uint32_t)((m0 + im * 16 + a_row) * 128 + a_c16 * 16);
    #pragma unroll
    for (int hb = 0; hb < 2; hb++)
        offB[hb] = (uint32_t)((n0w + hb * 16 + b_row) * 128 + b_c16 * 16);

    float c[4][4][4];
    #pragma unroll
    for (int im = 0; im < 4; im++)
        #pragma unroll
        for (int in = 0; in < 4; in++)
            #pragma unroll
            for (int q = 0; q < 4; q++) c[im][in][q] = 0.f;

    #pragma unroll
    for (int ks = 0; ks < 4; ks++) {
        const uint32_t ko = ks * 32;
        U4 A[4], Bh[2], Bl[2];
        #pragma unroll
        for (int hb = 0; hb < 2; hb++)
            Bh[hb] = ldmx4(smb + SMK_H + sw128(offB[hb] + ko));
        #pragma unroll
        for (int im = 0; im < 4; im++)
            A[im] = ldmx4(smb + SMQ_H + sw128(offA[im] + ko));
        #pragma unroll
        for (int im = 0; im < 4; im++) {
            mma16816(c[im][0], A[im], Bh[0].x, Bh[0].y);
            mma16816(c[im][1], A[im], Bh[0].z, Bh[0].w);
            mma16816(c[im][2], A[im], Bh[1].x, Bh[1].y);
            mma16816(c[im][3], A[im], Bh[1].z, Bh[1].w);
        }
        #pragma unroll
        for (int hb = 0; hb < 2; hb++)
            Bl[hb] = ldmx4(smb + SMK_L + sw128(offB[hb] + ko));
        #pragma unroll
        for (int im = 0; im < 4; im++) {
            mma16816(c[im][0], A[im], Bl[0].x, Bl[0].y);
            mma16816(c[im][1], A[im], Bl[0].z, Bl[0].w);
            mma16816(c[im][2], A[im], Bl[1].x, Bl[1].y);
            mma16816(c[im][3], A[im], Bl[1].z, Bl[1].w);
        }
        #pragma unroll
        for (int im = 0; im < 4; im++)
            A[im] = ldmx4(smb + SMQ_L + sw128(offA[im] + ko));
        #pragma unroll
        for (int im = 0; im < 4; im++) {
            mma16816(c[im][0], A[im], Bh[0].x, Bh[0].y);
            mma16816(c[im][1], A[im], Bh[0].z, Bh[0].w);
            mma16816(c[im][2], A[im], Bh[1].x, Bh[1].y);
            mma16816(c[im][3], A[im], Bh[1].z, Bh[1].w);
        }
    }

    // ---- epilogue: mask + exp in regs, rowsums, DIRECT float2 stores ----
    #pragma unroll
    for (int im = 0; im < 4; im++) {
        const int lrA = m0 + im * 16 + g;
        const int lrB = lrA + 8;
        const int rowA = row0 + lrA, rowB = row0 + lrB;
        float sA = 0.f, sB = 0.f;
        #pragma unroll
        for (int in = 0; in < 4; in++) {
            const int cb = n0w + in * 8 + 2 * t;
            const int colX = col0 + cb, colY = colX + 1;
            float e0 = (colX <= rowA) ? __expf(SCALE * c[im][in][0]) : 0.f;
            float e1 = (colY <= rowA) ? __expf(SCALE * c[im][in][1]) : 0.f;
            float e2 = (colX <= rowB) ? __expf(SCALE * c[im][in][2]) : 0.f;
            float e3 = (colY <= rowB) ? __expf(SCALE * c[im][in][3]) : 0.f;
            sA += e0 + e1; sB += e2 + e3;
            *(float2*)(S + (size_t)rowA * LL + colX) = make_float2(e0, e1);
            *(float2*)(S + (size_t)rowB * LL + colX) = make_float2(e2, e3);
        }
        sA += __shfl_xor_sync(0xffffffffu, sA, 1);
        sA += __shfl_xor_sync(0xffffffffu, sA, 2);
        sB += __shfl_xor_sync(0xffffffffu, sB, 1);
        sB += __shfl_xor_sync(0xffffffffu, sB, 2);
        if (t == 0) { rs[lrA][warp_n] = sA; rs[lrB][warp_n] = sB; }
    }
    __syncthreads();

    if (tid < 128)
        g_partial[((size_t)bh * LL + row0 + tid) * 8 + nt] =
            rs[tid][0] + rs[tid][1] + rs[tid][2] + rs[tid][3];
}

// ===========================================================================
// Kernel 2 (HMMA): normalize series in-place (P = E/rowsum) and O = P @ V.
// R11: unpaired tiles, 512 CTAs scheduled big-tile-first for balance.
// s-chunks of 64; double-buffered fp16 hi/lo staging; 1 sync/chunk.
// ===========================================================================
#define AV_BUF0   1024
#define AV_BUFSZ  49152
#define AV_PHO    0
#define AV_PLO    16384
#define AV_VHO    32768
#define AV_VLO    40960
#define AV_SMEM   (1024 + 2 * 49152)   // 99328 B

__device__ __forceinline__ void av_stage(
    const float4* e, const float4* vv, float* __restrict__ S,
    const float* __restrict__ rinv, char* __restrict__ buf,
    int row0, int s0, int tid) {
    char* Ph = buf + AV_PHO;
    char* Pl = buf + AV_PLO;
    char* Vh = buf + AV_VHO;
    char* Vl = buf + AV_VLO;
    #pragma unroll
    for (int it = 0; it < 8; it++) {
        int flat = it * 256 + tid;      // 2048 float4 = 128 x 16
        int c4 = flat & 15;
        int m  = flat >> 4;
        float r = rinv[m];
        float4 v = e[it];
        v.x *= r; v.y *= r; v.z *= r; v.w *= r;
        *(float4*)(S + (size_t)(row0 + m) * LL + s0 + c4 * 4) = v;
        uint32_t so = sw128((uint32_t)(m * 128 + c4 * 8));
        half hx = __float2half_rn(v.x), hy = __float2half_rn(v.y);
        half hz = __float2half_rn(v.z), hw = __float2half_rn(v.w);
        *(uint2*)(Ph + so) = make_uint2(pack2h(hx, hy), pack2h(hz, hw));
        *(uint2*)(Pl + so) = make_uint2(
            pack2h(__float2half_rn(v.x - __half2float(hx)),
                   __float2half_rn(v.y - __half2float(hy))),
            pack2h(__float2half_rn(v.z - __half2float(hz)),
                   __float2half_rn(v.w - __half2float(hw))));
    }
    #pragma unroll
    for (int it = 0; it < 4; it++) {
        int flat = it * 256 + tid;      // 1024 float4 = 64 x 16
        int c4 = flat & 15;
        int s  = flat >> 4;
        float4 w = vv[it];
        uint32_t so = sw128((uint32_t)(s * 128 + c4 * 8));
        half vx = __float2half_rn(w.x), vy = __float2half_rn(w.y);
        half vz = __float2half_rn(w.z), vw = __float2half_rn(w.w);
        *(uint2*)(Vh + so) = make_uint2(pack2h(vx, vy), pack2h(vz, vw));
        *(uint2*)(Vl + so) = make_uint2(
            pack2h(__float2half_rn(w.x - __half2float(vx)),
                   __float2half_rn(w.y - __half2float(vy))),
            pack2h(__float2half_rn(w.z - __half2float(vz)),
                   __float2half_rn(w.w - __half2float(vw))));
    }
}

__global__ __launch_bounds__(256, 2)
void k_av(const float* __restrict__ V, float* __restrict__ series,
          float* __restrict__ outV) {
    extern __shared__ __align__(1024) char avsm[];
    const int bx = blockIdx.x;
    const int mt = 7 - (bx >> 6);       // big tiles first
    const int bh = bx & 63;
    const int b  = bh >> 3;
    const int h  = bh & 7;
    const int tid = threadIdx.x;
    const int wid = tid >> 5, lane = tid & 31;
    const int warp_m = wid & 3, warp_n = wid >> 2;
    const int m0 = warp_m * 32, n0 = warp_n * 32;
    const int g = lane >> 2, t = lane & 3;

    float* rinv = (float*)avsm;
    const uint32_t smb = smem_u32(avsm);

    float* S = series + (size_t)bh * LL * LL;
    const float* Vg = V + (size_t)b * LL * (HH * DD) + h * DD;

    const int a_row = (lane & 7) + ((lane >> 3) & 1) * 8;
    const int a_c16 = (lane >> 4) & 1;
    const int v_row = (lane & 7) + ((lane >> 3) & 1) * 8;
    const int v_n8  = (lane >> 4) & 1;

    uint32_t offA[2], offVb[2];
    #pragma unroll
    for (int im = 0; im < 2; im++)
        offA[im] = (uint32_t)((m0 + im * 16 + a_row) * 128 + a_c16 * 16);
    #pragma unroll
    for (int in16 = 0; in16 < 2; in16++)
        offVb[in16] = (uint32_t)(v_row * 128 + n0 * 2 + in16 * 32 + v_n8 * 16);

    const int row0 = mt * 128;
    const int nchunks = 2 * (mt + 1);   // s-chunks of 64

    if (tid < 128) {
        float s = 0.f;
        for (int nt = 0; nt <= mt; nt++)
            s += g_partial[((size_t)bh * LL + row0 + tid) * 8 + nt];
        rinv[tid] = 1.0f / s;
    }
    __syncthreads();

    float c[2][4][4];
    #pragma unroll
    for (int im = 0; im < 2; im++)
        #pragma unroll
        for (int in = 0; in < 4; in++)
            #pragma unroll
            for (int q = 0; q < 4; q++) c[im][in][q] = 0.f;

    float4 e[8], vv[4];

    {   // prolog: chunk 0 -> buffer 0
        const int s0 = mt * 128;
        #pragma unroll
        for (int it = 0; it < 8; it++) {
            int flat = it * 256 + tid;
            int c4 = flat & 15;
            int m  = flat >> 4;
            e[it] = *(const float4*)(S + (size_t)(row0 + m) * LL + s0 + c4 * 4);
        }
        #pragma unroll
        for (int it = 0; it < 4; it++) {
            int flat = it * 256 + tid;
            int c4 = flat & 15;
            int s  = flat >> 4;
            vv[it] = *(const float4*)(Vg + (size_t)(s0 + s) * 512 + c4 * 4);
        }
        av_stage(e, vv, S, rinv, avsm + AV_BUF0, row0, s0, tid);
    }
    __syncthreads();

    for (int cc = 0; cc < nchunks; cc++) {
        const int buf = cc & 1;
        const bool more = (cc + 1 < nchunks);
        int s0n = 0;
        if (more) {
            const int cn = cc + 1;
            const int ntn = mt - (cn >> 1);
            s0n = ntn * 128 + (cn & 1) * 64;
            #pragma unroll
            for (int it = 0; it < 8; it++) {
                int flat = it * 256 + tid;
                int c4 = flat & 15;
                int m  = flat >> 4;
                e[it] = *(const float4*)(S + (size_t)(row0 + m) * LL + s0n + c4 * 4);
            }
            #pragma unroll
            for (int it = 0; it < 4; it++) {
                int flat = it * 256 + tid;
                int c4 = flat & 15;
                int s  = flat >> 4;
                vv[it] = *(const float4*)(Vg + (size_t)(s0n + s) * 512 + c4 * 4);
            }
        }

        // ---- compute current buffer ----
        {
            const uint32_t base = smb + AV_BUF0 + buf * AV_BUFSZ;
            #pragma unroll
            for (int ks = 0; ks < 4; ks++) {
                const uint32_t ko = ks * 32;        // A k-byte offset
                const uint32_t vr = ks * 2048;      // V row offset (16 rows)
                U4 A[2], Bh[2], Bl[2];
                #pragma unroll
                for (int in16 = 0; in16 < 2; in16++)
                    Bh[in16] = ldmx4t(base + AV_VHO + sw128(offVb[in16] + vr));
                #pragma unroll
                for (int im = 0; im < 2; im++)
                    A[im] = ldmx4(base + AV_PHO + sw128(offA[im] + ko));
                #pragma unroll
                for (int im = 0; im < 2; im++) {
                    mma16816(c[im][0], A[im], Bh[0].x, Bh[0].y);
                    mma16816(c[im][1], A[im], Bh[0].z, Bh[0].w);
                    mma16816(c[im][2], A[im], Bh[1].x, Bh[1].y);
                    mma16816(c[im][3], A[im], Bh[1].z, Bh[1].w);
                }
                #pragma unroll
                for (int in16 = 0; in16 < 2; in16++)
                    Bl[in16] = ldmx4t(base + AV_VLO + sw128(offVb[in16] + vr));
                #pragma unroll
                for (int im = 0; im < 2; im++) {
                    mma16816(c[im][0], A[im], Bl[0].x, Bl[0].y);
                    mma16816(c[im][1], A[im], Bl[0].z, Bl[0].w);
                    mma16816(c[im][2], A[im], Bl[1].x, Bl[1].y);
                    mma16816(c[im][3], A[im], Bl[1].z, Bl[1].w);
                }
                #pragma unroll
                for (int im = 0; im < 2; im++)
                    A[im] = ldmx4(base + AV_PLO + sw128(offA[im] + ko));
                #pragma unroll
                for (int im = 0; im < 2; im++) {
                    mma16816(c[im][0], A[im], Bh[0].x, Bh[0].y);
                    mma16816(c[im][1], A[im], Bh[0].z, Bh[0].w);
                    mma16816(c[im][2], A[im], Bh[1].x, Bh[1].y);
                    mma16816(c[im][3], A[im], Bh[1].z, Bh[1].w);
                }
            }
        }

        if (more)
            av_stage(e, vv, S, rinv, avsm + AV_BUF0 + (buf ^ 1) * AV_BUFSZ,
                     row0, s0n, tid);
        __syncthreads();
    }

    // ---- output O tile ----
    float* Og = outV + (size_t)b * LL * (HH * DD) + h * DD;
    #pragma unroll
    for (int im = 0; im < 2; im++) {
        const int rowA = row0 + m0 + im * 16 + g;
        const int rowB = rowA + 8;
        #pragma unroll
        for (int in = 0; in < 4; in++) {
            const int col = n0 + in * 8 + 2 * t;
            *(float2*)(Og + (size_t)rowA * 512 + col) =
                make_float2(c[im][in][0], c[im][in][1]);
            *(float2*)(Og + (size_t)rowB * 512 + col) =
                make_float2(c[im][in][2], c[im][in][3]);
        }
    }
}

// ---------------------------------------------------------------------------
extern "C" void kernel_launch(void* const* d_in, const int* in_sizes, int n_in,
                              void* d_out, int out_size) {
    (void)in_sizes; (void)n_in; (void)out_size;
    const float* Q   = (const float*)d_in[0];
    const float* K   = (const float*)d_in[1];
    const float* V   = (const float*)d_in[2];
    const float* sig = (const float*)d_in[3];
    float* out    = (float*)d_out;
    float* outV   = out;                 // (B,L,H,D)
    float* series = out + OFF_SERIES;    // (B,H,L,S)
    float* prior  = out + OFF_PRIOR;     // (B,L,S)

    cudaFuncSetAttribute(k_scores, cudaFuncAttributeMaxDynamicSharedMemorySize,
                         KS_SMEM);
    cudaFuncSetAttribute(k_av, cudaFuncAttributeMaxDynamicSharedMemorySize,
                         AV_SMEM);

    k_scores<<<dim3(8, 8, Bb * HH + 4), 256, KS_SMEM>>>(Q, K, series, sig, prior);
    k_av    <<<dim3(512, 1),           256, AV_SMEM>>>(V, series, outV);
}

// round 15
// speedup vs baseline: 1.2292x; 1.0319x over previous
#include <cuda_runtime.h>
#include <cuda_bf16.h>
#include <cuda_fp16.h>
#include <cstdint>

// Problem constants
#define Bb 8
#define LL 1024
#define HH 8
#define EE 64
#define DD 64
#define SCALE 0.125f   // 1/sqrt(64)

// Output layout (concatenated flattened tuple):
//   V:      (B,L,H,D)   at 0              size 4,194,304
//   series: (B,H,L,S)   at 4,194,304      size 67,108,864
//   prior:  (B,L,S)     at 71,303,168     size 8,388,608
#define OFF_SERIES 4194304
#define OFF_PRIOR  71303168

// Scratch: per-(b,h,row,ntile) partial row sums of unnormalized exp scores.
__device__ float g_partial[Bb * HH * LL * 8];  // 2 MB

// ---------------- warp-MMA helpers (sm_80-era PTX, sm_103-portable) --------
struct U4 { uint32_t x, y, z, w; };

__device__ __forceinline__ U4 ldmx4(uint32_t a) {
    U4 r;
    asm volatile("ldmatrix.sync.aligned.m8n8.x4.shared.b16 {%0,%1,%2,%3}, [%4];"
                 : "=r"(r.x), "=r"(r.y), "=r"(r.z), "=r"(r.w) : "r"(a));
    return r;
}
__device__ __forceinline__ U4 ldmx4t(uint32_t a) {
    U4 r;
    asm volatile("ldmatrix.sync.aligned.m8n8.x4.trans.shared.b16 {%0,%1,%2,%3}, [%4];"
                 : "=r"(r.x), "=r"(r.y), "=r"(r.z), "=r"(r.w) : "r"(a));
    return r;
}
__device__ __forceinline__ void mma16816(float* c, const U4& a,
                                         uint32_t b0, uint32_t b1) {
    asm volatile("mma.sync.aligned.m16n8k16.row.col.f32.f16.f16.f32 "
                 "{%0,%1,%2,%3}, {%4,%5,%6,%7}, {%8,%9}, {%0,%1,%2,%3};"
                 : "+f"(c[0]), "+f"(c[1]), "+f"(c[2]), "+f"(c[3])
                 : "r"(a.x), "r"(a.y), "r"(a.z), "r"(a.w), "r"(b0), "r"(b1));
}
__device__ __forceinline__ uint32_t pack2h(half a, half b) {
    return (uint32_t)__half_as_ushort(a) | ((uint32_t)__half_as_ushort(b) << 16);
}
__device__ __forceinline__ uint32_t smem_u32(const void* p) {
    uint32_t a;
    asm("{ .reg .u64 t; cvta.to.shared.u64 t, %1; cvt.u32.u64 %0, t; }"
        : "=r"(a) : "l"(p));
    return a;
}
// SW128 swizzle (Swizzle<3,4,3>) on byte offsets within a 128B-row tile
__device__ __forceinline__ uint32_t sw128(uint32_t off) {
    return off ^ ((off >> 3) & 0x70);
}

// ===========================================================================
// Kernel 1 (HMMA + fused prior): grid (8, 8, 4+64).
//   z < 4  : prior-association blocks (long-running; scheduled FIRST so they
//            overlap the whole scores kernel instead of forming a tail)
//   z >= 4 : E = exp(scale * Q K^T) causal tile (bh = z-4; R11 path)
// ===========================================================================
#define SMQ_H 0
#define SMQ_L 16384
#define SMK_H 32768
#define SMK_L 49152
#define KS_SMEM 65536

__global__ __launch_bounds__(256, 2)
void k_scores(const float* __restrict__ Q, const float* __restrict__ K,
              float* __restrict__ series,
              const float* __restrict__ sigma, float* __restrict__ prior) {
    extern __shared__ __align__(1024) char dsm[];
    const int tid = threadIdx.x;

    // ---------------- prior path (z = 0..3) ----------------
    if (blockIdx.z < 4) {
        const int flat = blockIdx.z * 64 + blockIdx.y * 8 + blockIdx.x;
        const int i0 = (flat >> 3) * 32;
        const int b  = flat & 7;
        float* rl  = (float*)dsm;              // [8][1024]
        float* red = (float*)(dsm + 32768);    // [8]

        for (int idx = tid; idx < 8 * 1024; idx += 256) {
            int hh = idx >> 10;
            int s  = idx & 1023;
            rl[hh * 1024 + s] = -1.0f / sigma[((size_t)b * 8 + hh) * 1024 + s];
        }
        __syncthreads();

        const int lane = tid & 31, wd = tid >> 5;
        for (int ii = 0; ii < 32; ii++) {
            const int i = i0 + ii;
            float p[4];
            float sum = 0.f;
            #pragma unroll
            for (int j = 0; j < 4; j++) {
                const int s = tid + j * 256;
                const float d = (float)((i > s) ? (i - s) : (s - i));
                float a = 0.f;
                #pragma unroll
                for (int hh = 0; hh < 8; hh++)
                    a += __expf(d * rl[hh * 1024 + s]);
                p[j] = a;
                sum += a;
            }
            #pragma unroll
            for (int off = 16; off; off >>= 1)
                sum += __shfl_xor_sync(0xffffffffu, sum, off);
            if (lane == 0) red[wd] = sum;
            __syncthreads();
            float tot = 0.f;
            #pragma unroll
            for (int w = 0; w < 8; w++) tot += red[w];
            const float inv = 1.0f / tot;
            float* dst = prior + (size_t)(b * 1024 + i) * 1024;
            #pragma unroll
            for (int j = 0; j < 4; j++)
                dst[tid + j * 256] = p[j] * inv;
            __syncthreads();
        }
        return;
    }

    // ---------------- scores path (z = 4..67) ----------------
    const int nt = blockIdx.x;
    const int mt = blockIdx.y;
    const int bh = blockIdx.z - 4;      // b*8 + h
    const int b  = bh >> 3;
    const int h  = bh & 7;

    float* S = series + (size_t)bh * LL * LL;
    const int row0 = mt * 128, col0 = nt * 128;

    if (nt > mt) {
        const float4 z = make_float4(0.f, 0.f, 0.f, 0.f);
        #pragma unroll
        for (int i = 0; i < 16; i++) {
            int flat = i * 256 + tid;
            int r = flat >> 5;
            int c = (flat & 31) << 2;
            *(float4*)(S + (size_t)(row0 + r) * LL + col0 + c) = z;
        }
        return;
    }

    __shared__ float rs[128][4];   // per-(row, warp_n) partial sums

    const uint32_t smb = smem_u32(dsm);
    const int wid = tid >> 5, lane = tid & 31;
    const int warp_m = wid & 1, warp_n = wid >> 1;
    const int m0 = warp_m * 64, n0w = warp_n * 32;
    const int g = lane >> 2, t = lane & 3;

    const float* Qg = Q + (size_t)b * LL * (HH * EE) + h * EE;  // + l*512 + e
    const float* Kg = K + (size_t)b * LL * (HH * EE) + h * EE;
    #pragma unroll
    for (int it = 0; it < 8; it++) {
        int flat = it * 256 + tid;      // 2048 float4 per matrix
        int c4 = flat & 15;
        int r  = flat >> 4;
        uint32_t so = sw128((uint32_t)(r * 128 + c4 * 8));

        float4 v = *(const float4*)(Qg + (size_t)(row0 + r) * 512 + c4 * 4);
        half hx = __float2half_rn(v.x), hy = __float2half_rn(v.y);
        half hz = __float2half_rn(v.z), hw = __float2half_rn(v.w);
        *(uint2*)(dsm + SMQ_H + so) = make_uint2(pack2h(hx, hy), pack2h(hz, hw));
        *(uint2*)(dsm + SMQ_L + so) = make_uint2(
            pack2h(__float2half_rn(v.x - __half2float(hx)),
                   __float2half_rn(v.y - __half2float(hy))),
            pack2h(__float2half_rn(v.z - __half2float(hz)),
                   __float2half_rn(v.w - __half2float(hw))));

        float4 w = *(const float4*)(Kg + (size_t)(col0 + r) * 512 + c4 * 4);
        half kx = __float2half_rn(w.x), ky = __float2half_rn(w.y);
        half kz = __float2half_rn(w.z), kw = __float2half_rn(w.w);
        *(uint2*)(dsm + SMK_H + so) = make_uint2(pack2h(kx, ky), pack2h(kz, kw));
        *(uint2*)(dsm + SMK_L + so) = make_uint2(
            pack2h(__float2half_rn(w.x - __half2float(kx)),
                   __float2half_rn(w.y - __half2float(ky))),
            pack2h(__float2half_rn(w.z - __half2float(kz)),
                   __float2half_rn(w.w - __half2float(kw))));
    }
    __syncthreads();

    const int a_row = (lane & 7) + ((lane >> 3) & 1) * 8;
    const int a_c16 = (lane >> 4) & 1;
    const int b_row = (lane & 7) + ((lane >> 4) & 1) * 8;
    const int b_c16 = (lane >> 3) & 1;

    uint32_t offA[4], offB[2];
    #pragma unroll
    for (int im = 0; im < 4; im++)
        offA[im] = (uint32_t)((m0 + im * 16 + a_row) * 128 + a_c16 * 16);
    #pragma unroll
    for (int hb = 0; hb < 2; hb++)
        offB[hb] = (uint32_t)((n0w + hb * 16 + b_row) * 128 + b_c16 * 16);

    float c[4][4][4];
    #pragma unroll
    for (int im = 0; im < 4; im++)
        #pragma unroll
        for (int in = 0; in < 4; in++)
            #pragma unroll
            for (int q = 0; q < 4; q++) c[im][in][q] = 0.f;

    #pragma unroll
    for (int ks = 0; ks < 4; ks++) {
        const uint32_t ko = ks * 32;
        U4 A[4], Bh[2], Bl[2];
        #pragma unroll
        for (int hb = 0; hb < 2; hb++)
            Bh[hb] = ldmx4(smb + SMK_H + sw128(offB[hb] + ko));
        #pragma unroll
        for (int im = 0; im < 4; im++)
            A[im] = ldmx4(smb + SMQ_H + sw128(offA[im] + ko));
        #pragma unroll
        for (int im = 0; im < 4; im++) {
            mma16816(c[im][0], A[im], Bh[0].x, Bh[0].y);
            mma16816(c[im][1], A[im], Bh[0].z, Bh[0].w);
            mma16816(c[im][2], A[im], Bh[1].x, Bh[1].y);
            mma16816(c[im][3], A[im], Bh[1].z, Bh[1].w);
        }
        #pragma unroll
        for (int hb = 0; hb < 2; hb++)
            Bl[hb] = ldmx4(smb + SMK_L + sw128(offB[hb] + ko));
        #pragma unroll
        for (int im = 0; im < 4; im++) {
            mma16816(c[im][0], A[im], Bl[0].x, Bl[0].y);
            mma16816(c[im][1], A[im], Bl[0].z, Bl[0].w);
            mma16816(c[im][2], A[im], Bl[1].x, Bl[1].y);
            mma16816(c[im][3], A[im], Bl[1].z, Bl[1].w);
        }
        #pragma unroll
        for (int im = 0; im < 4; im++)
            A[im] = ldmx4(smb + SMQ_L + sw128(offA[im] + ko));
        #pragma unroll
        for (int im = 0; im < 4; im++) {
            mma16816(c[im][0], A[im], Bh[0].x, Bh[0].y);
            mma16816(c[im][1], A[im], Bh[0].z, Bh[0].w);
            mma16816(c[im][2], A[im], Bh[1].x, Bh[1].y);
            mma16816(c[im][3], A[im], Bh[1].z, Bh[1].w);
        }
    }

    // ---- epilogue: mask + exp in regs, rowsums, DIRECT float2 stores ----
    #pragma unroll
    for (int im = 0; im < 4; im++) {
        const int lrA = m0 + im * 16 + g;
        const int lrB = lrA + 8;
        const int rowA = row0 + lrA, rowB = row0 + lrB;
        float sA = 0.f, sB = 0.f;
        #pragma unroll
        for (int in = 0; in < 4; in++) {
            const int cb = n0w + in * 8 + 2 * t;
            const int colX = col0 + cb, colY = colX + 1;
            float e0 = (colX <= rowA) ? __expf(SCALE * c[im][in][0]) : 0.f;
            float e1 = (colY <= rowA) ? __expf(SCALE * c[im][in][1]) : 0.f;
            float e2 = (colX <= rowB) ? __expf(SCALE * c[im][in][2]) : 0.f;
            float e3 = (colY <= rowB) ? __expf(SCALE * c[im][in][3]) : 0.f;
            sA += e0 + e1; sB += e2 + e3;
            *(float2*)(S + (size_t)rowA * LL + colX) = make_float2(e0, e1);
            *(float2*)(S + (size_t)rowB * LL + colX) = make_float2(e2, e3);
        }
        sA += __shfl_xor_sync(0xffffffffu, sA, 1);
        sA += __shfl_xor_sync(0xffffffffu, sA, 2);
        sB += __shfl_xor_sync(0xffffffffu, sB, 1);
        sB += __shfl_xor_sync(0xffffffffu, sB, 2);
        if (t == 0) { rs[lrA][warp_n] = sA; rs[lrB][warp_n] = sB; }
    }
    __syncthreads();

    if (tid < 128)
        g_partial[((size_t)bh * LL + row0 + tid) * 8 + nt] =
            rs[tid][0] + rs[tid][1] + rs[tid][2] + rs[tid][3];
}

// ===========================================================================
// Kernel 2 (HMMA): normalize series in-place (P = E/rowsum) and O = P @ V.
// Unpaired tiles, 512 CTAs scheduled big-tile-first; s-chunks of 64;
// double-buffered fp16 hi/lo staging; 1 sync/chunk. (R11/R14, unchanged)
// ===========================================================================
#define AV_BUF0   1024
#define AV_BUFSZ  49152
#define AV_PHO    0
#define AV_PLO    16384
#define AV_VHO    32768
#define AV_VLO    40960
#define AV_SMEM   (1024 + 2 * 49152)   // 99328 B

__device__ __forceinline__ void av_stage(
    const float4* e, const float4* vv, float* __restrict__ S,
    const float* __restrict__ rinv, char* __restrict__ buf,
    int row0, int s0, int tid) {
    char* Ph = buf + AV_PHO;
    char* Pl = buf + AV_PLO;
    char* Vh = buf + AV_VHO;
    char* Vl = buf + AV_VLO;
    #pragma unroll
    for (int it = 0; it < 8; it++) {
        int flat = it * 256 + tid;      // 2048 float4 = 128 x 16
        int c4 = flat & 15;
        int m  = flat >> 4;
        float r = rinv[m];
        float4 v = e[it];
        v.x *= r; v.y *= r; v.z *= r; v.w *= r;
        *(float4*)(S + (size_t)(row0 + m) * LL + s0 + c4 * 4) = v;
        uint32_t so = sw128((uint32_t)(m * 128 + c4 * 8));
        half hx = __float2half_rn(v.x), hy = __float2half_rn(v.y);
        half hz = __float2half_rn(v.z), hw = __float2half_rn(v.w);
        *(uint2*)(Ph + so) = make_uint2(pack2h(hx, hy), pack2h(hz, hw));
        *(uint2*)(Pl + so) = make_uint2(
            pack2h(__float2half_rn(v.x - __half2float(hx)),
                   __float2half_rn(v.y - __half2float(hy))),
            pack2h(__float2half_rn(v.z - __half2float(hz)),
                   __float2half_rn(v.w - __half2float(hw))));
    }
    #pragma unroll
    for (int it = 0; it < 4; it++) {
        int flat = it * 256 + tid;      // 1024 float4 = 64 x 16
        int c4 = flat & 15;
        int s  = flat >> 4;
        float4 w = vv[it];
        uint32_t so = sw128((uint32_t)(s * 128 + c4 * 8));
        half vx = __float2half_rn(w.x), vy = __float2half_rn(w.y);
        half vz = __float2half_rn(w.z), vw = __float2half_rn(w.w);
        *(uint2*)(Vh + so) = make_uint2(pack2h(vx, vy), pack2h(vz, vw));
        *(uint2*)(Vl + so) = make_uint2(
            pack2h(__float2half_rn(w.x - __half2float(vx)),
                   __float2half_rn(w.y - __half2float(vy))),
            pack2h(__float2half_rn(w.z - __half2float(vz)),
                   __float2half_rn(w.w - __half2float(vw))));
    }
}

__global__ __launch_bounds__(256, 2)
void k_av(const float* __restrict__ V, float* __restrict__ series,
          float* __restrict__ outV) {
    extern __shared__ __align__(1024) char avsm[];
    const int bx = blockIdx.x;
    const int mt = 7 - (bx >> 6);       // big tiles first
    const int bh = bx & 63;
    const int b  = bh >> 3;
    const int h  = bh & 7;
    const int tid = threadIdx.x;
    const int wid = tid >> 5, lane = tid & 31;
    const int warp_m = wid & 3, warp_n = wid >> 2;
    const int m0 = warp_m * 32, n0 = warp_n * 32;
    const int g = lane >> 2, t = lane & 3;

    float* rinv = (float*)avsm;
    const uint32_t smb = smem_u32(avsm);

    float* S = series + (size_t)bh * LL * LL;
    const float* Vg = V + (size_t)b * LL * (HH * DD) + h * DD;

    const int a_row = (lane & 7) + ((lane >> 3) & 1) * 8;
    const int a_c16 = (lane >> 4) & 1;
    const int v_row = (lane & 7) + ((lane >> 3) & 1) * 8;
    const int v_n8  = (lane >> 4) & 1;

    uint32_t offA[2], offVb[2];
    #pragma unroll
    for (int im = 0; im < 2; im++)
        offA[im] = (uint32_t)((m0 + im * 16 + a_row) * 128 + a_c16 * 16);
    #pragma unroll
    for (int in16 = 0; in16 < 2; in16++)
        offVb[in16] = (uint32_t)(v_row * 128 + n0 * 2 + in16 * 32 + v_n8 * 16);

    const int row0 = mt * 128;
    const int nchunks = 2 * (mt + 1);   // s-chunks of 64

    if (tid < 128) {
        float s = 0.f;
        for (int nt = 0; nt <= mt; nt++)
            s += g_partial[((size_t)bh * LL + row0 + tid) * 8 + nt];
        rinv[tid] = 1.0f / s;
    }
    __syncthreads();

    float c[2][4][4];
    #pragma unroll
    for (int im = 0; im < 2; im++)
        #pragma unroll
        for (int in = 0; in < 4; in++)
            #pragma unroll
            for (int q = 0; q < 4; q++) c[im][in][q] = 0.f;

    float4 e[8], vv[4];

    {   // prolog: chunk 0 -> buffer 0
        const int s0 = mt * 128;
        #pragma unroll
        for (int it = 0; it < 8; it++) {
            int flat = it * 256 + tid;
            int c4 = flat & 15;
            int m  = flat >> 4;
            e[it] = *(const float4*)(S + (size_t)(row0 + m) * LL + s0 + c4 * 4);
        }
        #pragma unroll
        for (int it = 0; it < 4; it++) {
            int flat = it * 256 + tid;
            int c4 = flat & 15;
            int s  = flat >> 4;
            vv[it] = *(const float4*)(Vg + (size_t)(s0 + s) * 512 + c4 * 4);
        }
        av_stage(e, vv, S, rinv, avsm + AV_BUF0, row0, s0, tid);
    }
    __syncthreads();

    for (int cc = 0; cc < nchunks; cc++) {
        const int buf = cc & 1;
        const bool more = (cc + 1 < nchunks);
        int s0n = 0;
        if (more) {
            const int cn = cc + 1;
            const int ntn = mt - (cn >> 1);
            s0n = ntn * 128 + (cn & 1) * 64;
            #pragma unroll
            for (int it = 0; it < 8; it++) {
                int flat = it * 256 + tid;
                int c4 = flat & 15;
                int m  = flat >> 4;
                e[it] = *(const float4*)(S + (size_t)(row0 + m) * LL + s0n + c4 * 4);
            }
            #pragma unroll
            for (int it = 0; it < 4; it++) {
                int flat = it * 256 + tid;
                int c4 = flat & 15;
                int s  = flat >> 4;
                vv[it] = *(const float4*)(Vg + (size_t)(s0n + s) * 512 + c4 * 4);
            }
        }

        // ---- compute current buffer ----
        {
            const uint32_t base = smb + AV_BUF0 + buf * AV_BUFSZ;
            #pragma unroll
            for (int ks = 0; ks < 4; ks++) {
                const uint32_t ko = ks * 32;        // A k-byte offset
                const uint32_t vr = ks * 2048;      // V row offset (16 rows)
                U4 A[2], Bh[2], Bl[2];
                #pragma unroll
                for (int in16 = 0; in16 < 2; in16++)
                    Bh[in16] = ldmx4t(base + AV_VHO + sw128(offVb[in16] + vr));
                #pragma unroll
                for (int im = 0; im < 2; im++)
                    A[im] = ldmx4(base + AV_PHO + sw128(offA[im] + ko));
                #pragma unroll
                for (int im = 0; im < 2; im++) {
                    mma16816(c[im][0], A[im], Bh[0].x, Bh[0].y);
                    mma16816(c[im][1], A[im], Bh[0].z, Bh[0].w);
                    mma16816(c[im][2], A[im], Bh[1].x, Bh[1].y);
                    mma16816(c[im][3], A[im], Bh[1].z, Bh[1].w);
                }
                #pragma unroll
                for (int in16 = 0; in16 < 2; in16++)
                    Bl[in16] = ldmx4t(base + AV_VLO + sw128(offVb[in16] + vr));
                #pragma unroll
                for (int im = 0; im < 2; im++) {
                    mma16816(c[im][0], A[im], Bl[0].x, Bl[0].y);
                    mma16816(c[im][1], A[im], Bl[0].z, Bl[0].w);
                    mma16816(c[im][2], A[im], Bl[1].x, Bl[1].y);
                    mma16816(c[im][3], A[im], Bl[1].z, Bl[1].w);
                }
                #pragma unroll
                for (int im = 0; im < 2; im++)
                    A[im] = ldmx4(base + AV_PLO + sw128(offA[im] + ko));
                #pragma unroll
                for (int im = 0; im < 2; im++) {
                    mma16816(c[im][0], A[im], Bh[0].x, Bh[0].y);
                    mma16816(c[im][1], A[im], Bh[0].z, Bh[0].w);
                    mma16816(c[im][2], A[im], Bh[1].x, Bh[1].y);
                    mma16816(c[im][3], A[im], Bh[1].z, Bh[1].w);
                }
            }
        }

        if (more)
            av_stage(e, vv, S, rinv, avsm + AV_BUF0 + (buf ^ 1) * AV_BUFSZ,
                     row0, s0n, tid);
        __syncthreads();
    }

    // ---- output O tile ----
    float* Og = outV + (size_t)b * LL * (HH * DD) + h * DD;
    #pragma unroll
    for (int im = 0; im < 2; im++) {
        const int rowA = row0 + m0 + im * 16 + g;
        const int rowB = rowA + 8;
        #pragma unroll
        for (int in = 0; in < 4; in++) {
            const int col = n0 + in * 8 + 2 * t;
            *(float2*)(Og + (size_t)rowA * 512 + col) =
                make_float2(c[im][in][0], c[im][in][1]);
            *(float2*)(Og + (size_t)rowB * 512 + col) =
                make_float2(c[im][in][2], c[im][in][3]);
        }
    }
}

// ---------------------------------------------------------------------------
extern "C" void kernel_launch(void* const* d_in, const int* in_sizes, int n_in,
                              void* d_out, int out_size) {
    (void)in_sizes; (void)n_in; (void)out_size;
    const float* Q   = (const float*)d_in[0];
    const float* K   = (const float*)d_in[1];
    const float* V   = (const float*)d_in[2];
    const float* sig = (const float*)d_in[3];
    float* out    = (float*)d_out;
    float* outV   = out;                 // (B,L,H,D)
    float* series = out + OFF_SERIES;    // (B,H,L,S)
    float* prior  = out + OFF_PRIOR;     // (B,L,S)

    cudaFuncSetAttribute(k_scores, cudaFuncAttributeMaxDynamicSharedMemorySize,
                         KS_SMEM);
    cudaFuncSetAttribute(k_av, cudaFuncAttributeMaxDynamicSharedMemorySize,
                         AV_SMEM);

    k_scores<<<dim3(8, 8, 4 + Bb * HH), 256, KS_SMEM>>>(Q, K, series, sig, prior);
    k_av    <<<dim3(512, 1),           256, AV_SMEM>>>(V, series, outV);
}

// round 16
// speedup vs baseline: 1.2614x; 1.0261x over previous
#include <cuda_runtime.h>
#include <cuda_bf16.h>
#include <cuda_fp16.h>
#include <cstdint>

// Problem constants
#define Bb 8
#define LL 1024
#define HH 8
#define EE 64
#define DD 64
#define SCALE 0.125f   // 1/sqrt(64)

// Output layout (concatenated flattened tuple):
//   V:      (B,L,H,D)   at 0              size 4,194,304
//   series: (B,H,L,S)   at 4,194,304      size 67,108,864
//   prior:  (B,L,S)     at 71,303,168     size 8,388,608
#define OFF_SERIES 4194304
#define OFF_PRIOR  71303168

// Scratch: per-(b,h,row,ntile) partial row sums of rounded exp scores.
__device__ float g_partial[Bb * HH * LL * 8];          // 2 MB
// Scratch: causal E tiles in fp16 (upper triangle never touched).
__device__ __half g_eh[(size_t)Bb * HH * LL * LL];     // 128 MB

// ---------------- warp-MMA helpers (sm_80-era PTX, sm_103-portable) --------
struct U4 { uint32_t x, y, z, w; };

__device__ __forceinline__ U4 ldmx4(uint32_t a) {
    U4 r;
    asm volatile("ldmatrix.sync.aligned.m8n8.x4.shared.b16 {%0,%1,%2,%3}, [%4];"
                 : "=r"(r.x), "=r"(r.y), "=r"(r.z), "=r"(r.w) : "r"(a));
    return r;
}
__device__ __forceinline__ U4 ldmx4t(uint32_t a) {
    U4 r;
    asm volatile("ldmatrix.sync.aligned.m8n8.x4.trans.shared.b16 {%0,%1,%2,%3}, [%4];"
                 : "=r"(r.x), "=r"(r.y), "=r"(r.z), "=r"(r.w) : "r"(a));
    return r;
}
__device__ __forceinline__ void mma16816(float* c, const U4& a,
                                         uint32_t b0, uint32_t b1) {
    asm volatile("mma.sync.aligned.m16n8k16.row.col.f32.f16.f16.f32 "
                 "{%0,%1,%2,%3}, {%4,%5,%6,%7}, {%8,%9}, {%0,%1,%2,%3};"
                 : "+f"(c[0]), "+f"(c[1]), "+f"(c[2]), "+f"(c[3])
                 : "r"(a.x), "r"(a.y), "r"(a.z), "r"(a.w), "r"(b0), "r"(b1));
}
__device__ __forceinline__ uint32_t pack2h(half a, half b) {
    return (uint32_t)__half_as_ushort(a) | ((uint32_t)__half_as_ushort(b) << 16);
}
__device__ __forceinline__ uint32_t smem_u32(const void* p) {
    uint32_t a;
    asm("{ .reg .u64 t; cvta.to.shared.u64 t, %1; cvt.u32.u64 %0, t; }"
        : "=r"(a) : "l"(p));
    return a;
}
// SW128 swizzle (Swizzle<3,4,3>) on byte offsets within a 128B-row tile
__device__ __forceinline__ uint32_t sw128(uint32_t off) {
    return off ^ ((off >> 3) & 0x70);
}

// ===========================================================================
// Kernel 1 (HMMA + fused prior): grid (8, 8, 4+64).
//   z < 4  : prior-association blocks (long-running; scheduled FIRST)
//   z >= 4 : causal tile: E' = fp16(exp(scale*QK^T)) -> g_eh; rowsums of E'.
//            Upper tiles: zero-fill series.
// ===========================================================================
#define SMQ_H 0
#define SMQ_L 16384
#define SMK_H 32768
#define SMK_L 49152
#define KS_SMEM 65536

__global__ __launch_bounds__(256, 2)
void k_scores(const float* __restrict__ Q, const float* __restrict__ K,
              float* __restrict__ series,
              const float* __restrict__ sigma, float* __restrict__ prior) {
    extern __shared__ __align__(1024) char dsm[];
    const int tid = threadIdx.x;

    // ---------------- prior path (z = 0..3) ----------------
    if (blockIdx.z < 4) {
        const int flat = blockIdx.z * 64 + blockIdx.y * 8 + blockIdx.x;
        const int i0 = (flat >> 3) * 32;
        const int b  = flat & 7;
        float* rl  = (float*)dsm;              // [8][1024]
        float* red = (float*)(dsm + 32768);    // [8]

        for (int idx = tid; idx < 8 * 1024; idx += 256) {
            int hh = idx >> 10;
            int s  = idx & 1023;
            rl[hh * 1024 + s] = -1.0f / sigma[((size_t)b * 8 + hh) * 1024 + s];
        }
        __syncthreads();

        const int lane = tid & 31, wd = tid >> 5;
        for (int ii = 0; ii < 32; ii++) {
            const int i = i0 + ii;
            float p[4];
            float sum = 0.f;
            #pragma unroll
            for (int j = 0; j < 4; j++) {
                const int s = tid + j * 256;
                const float d = (float)((i > s) ? (i - s) : (s - i));
                float a = 0.f;
                #pragma unroll
                for (int hh = 0; hh < 8; hh++)
                    a += __expf(d * rl[hh * 1024 + s]);
                p[j] = a;
                sum += a;
            }
            #pragma unroll
            for (int off = 16; off; off >>= 1)
                sum += __shfl_xor_sync(0xffffffffu, sum, off);
            if (lane == 0) red[wd] = sum;
            __syncthreads();
            float tot = 0.f;
            #pragma unroll
            for (int w = 0; w < 8; w++) tot += red[w];
            const float inv = 1.0f / tot;
            float* dst = prior + (size_t)(b * 1024 + i) * 1024;
            #pragma unroll
            for (int j = 0; j < 4; j++)
                dst[tid + j * 256] = p[j] * inv;
            __syncthreads();
        }
        return;
    }

    // ---------------- scores path (z = 4..67) ----------------
    const int nt = blockIdx.x;
    const int mt = blockIdx.y;
    const int bh = blockIdx.z - 4;      // b*8 + h
    const int b  = bh >> 3;
    const int h  = bh & 7;

    float* S = series + (size_t)bh * LL * LL;
    const int row0 = mt * 128, col0 = nt * 128;

    if (nt > mt) {
        const float4 z = make_float4(0.f, 0.f, 0.f, 0.f);
        #pragma unroll
        for (int i = 0; i < 16; i++) {
            int flat = i * 256 + tid;
            int r = flat >> 5;
            int c = (flat & 31) << 2;
            *(float4*)(S + (size_t)(row0 + r) * LL + col0 + c) = z;
        }
        return;
    }

    __shared__ float rs[128][4];   // per-(row, warp_n) partial sums

    const uint32_t smb = smem_u32(dsm);
    const int wid = tid >> 5, lane = tid & 31;
    const int warp_m = wid & 1, warp_n = wid >> 1;
    const int m0 = warp_m * 64, n0w = warp_n * 32;
    const int g = lane >> 2, t = lane & 3;

    const float* Qg = Q + (size_t)b * LL * (HH * EE) + h * EE;  // + l*512 + e
    const float* Kg = K + (size_t)b * LL * (HH * EE) + h * EE;
    #pragma unroll
    for (int it = 0; it < 8; it++) {
        int flat = it * 256 + tid;      // 2048 float4 per matrix
        int c4 = flat & 15;
        int r  = flat >> 4;
        uint32_t so = sw128((uint32_t)(r * 128 + c4 * 8));

        float4 v = *(const float4*)(Qg + (size_t)(row0 + r) * 512 + c4 * 4);
        half hx = __float2half_rn(v.x), hy = __float2half_rn(v.y);
        half hz = __float2half_rn(v.z), hw = __float2half_rn(v.w);
        *(uint2*)(dsm + SMQ_H + so) = make_uint2(pack2h(hx, hy), pack2h(hz, hw));
        *(uint2*)(dsm + SMQ_L + so) = make_uint2(
            pack2h(__float2half_rn(v.x - __half2float(hx)),
                   __float2half_rn(v.y - __half2float(hy))),
            pack2h(__float2half_rn(v.z - __half2float(hz)),
                   __float2half_rn(v.w - __half2float(hw))));

        float4 w = *(const float4*)(Kg + (size_t)(col0 + r) * 512 + c4 * 4);
        half kx = __float2half_rn(w.x), ky = __float2half_rn(w.y);
        half kz = __float2half_rn(w.z), kw = __float2half_rn(w.w);
        *(uint2*)(dsm + SMK_H + so) = make_uint2(pack2h(kx, ky), pack2h(kz, kw));
        *(uint2*)(dsm + SMK_L + so) = make_uint2(
            pack2h(__float2half_rn(w.x - __half2float(kx)),
                   __float2half_rn(w.y - __half2float(ky))),
            pack2h(__float2half_rn(w.z - __half2float(kz)),
                   __float2half_rn(w.w - __half2float(kw))));
    }
    __syncthreads();

    const int a_row = (lane & 7) + ((lane >> 3) & 1) * 8;
    const int a_c16 = (lane >> 4) & 1;
    const int b_row = (lane & 7) + ((lane >> 4) & 1) * 8;
    const int b_c16 = (lane >> 3) & 1;

    uint32_t offA[4], offB[2];
    #pragma unroll
    for (int im = 0; im < 4; im++)
        offA[im] = (uint32_t)((m0 + im * 16 + a_row) * 128 + a_c16 * 16);
    #pragma unroll
    for (int hb = 0; hb < 2; hb++)
        offB[hb] = (uint32_t)((n0w + hb * 16 + b_row) * 128 + b_c16 * 16);

    float c[4][4][4];
    #pragma unroll
    for (int im = 0; im < 4; im++)
        #pragma unroll
        for (int in = 0; in < 4; in++)
            #pragma unroll
            for (int q = 0; q < 4; q++) c[im][in][q] = 0.f;

    #pragma unroll
    for (int ks = 0; ks < 4; ks++) {
        const uint32_t ko = ks * 32;
        U4 A[4], Bh[2], Bl[2];
        #pragma unroll
        for (int hb = 0; hb < 2; hb++)
            Bh[hb] = ldmx4(smb + SMK_H + sw128(offB[hb] + ko));
        #pragma unroll
        for (int im = 0; im < 4; im++)
            A[im] = ldmx4(smb + SMQ_H + sw128(offA[im] + ko));
        #pragma unroll
        for (int im = 0; im < 4; im++) {
            mma16816(c[im][0], A[im], Bh[0].x, Bh[0].y);
            mma16816(c[im][1], A[im], Bh[0].z, Bh[0].w);
            mma16816(c[im][2], A[im], Bh[1].x, Bh[1].y);
            mma16816(c[im][3], A[im], Bh[1].z, Bh[1].w);
        }
        #pragma unroll
        for (int hb = 0; hb < 2; hb++)
            Bl[hb] = ldmx4(smb + SMK_L + sw128(offB[hb] + ko));
        #pragma unroll
        for (int im = 0; im < 4; im++) {
            mma16816(c[im][0], A[im], Bl[0].x, Bl[0].y);
            mma16816(c[im][1], A[im], Bl[0].z, Bl[0].w);
            mma16816(c[im][2], A[im], Bl[1].x, Bl[1].y);
            mma16816(c[im][3], A[im], Bl[1].z, Bl[1].w);
        }
        #pragma unroll
        for (int im = 0; im < 4; im++)
            A[im] = ldmx4(smb + SMQ_L + sw128(offA[im] + ko));
        #pragma unroll
        for (int im = 0; im < 4; im++) {
            mma16816(c[im][0], A[im], Bh[0].x, Bh[0].y);
            mma16816(c[im][1], A[im], Bh[0].z, Bh[0].w);
            mma16816(c[im][2], A[im], Bh[1].x, Bh[1].y);
            mma16816(c[im][3], A[im], Bh[1].z, Bh[1].w);
        }
    }

    // ---- epilogue: mask + exp; round to fp16; rowsums of ROUNDED values;
    //      store fp16 E' to scratch (series untouched for causal tiles) ----
    __half* EH = g_eh + (size_t)bh * LL * LL;
    #pragma unroll
    for (int im = 0; im < 4; im++) {
        const int lrA = m0 + im * 16 + g;
        const int lrB = lrA + 8;
        const int rowA = row0 + lrA, rowB = row0 + lrB;
        float sA = 0.f, sB = 0.f;
        #pragma unroll
        for (int in = 0; in < 4; in++) {
            const int cb = n0w + in * 8 + 2 * t;
            const int colX = col0 + cb, colY = colX + 1;
            float e0 = (colX <= rowA) ? __expf(SCALE * c[im][in][0]) : 0.f;
            float e1 = (colY <= rowA) ? __expf(SCALE * c[im][in][1]) : 0.f;
            float e2 = (colX <= rowB) ? __expf(SCALE * c[im][in][2]) : 0.f;
            float e3 = (colY <= rowB) ? __expf(SCALE * c[im][in][3]) : 0.f;
            half h0 = __float2half_rn(e0), h1 = __float2half_rn(e1);
            half h2 = __float2half_rn(e2), h3 = __float2half_rn(e3);
            sA += __half2float(h0) + __half2float(h1);
            sB += __half2float(h2) + __half2float(h3);
            *(uint32_t*)(EH + (size_t)rowA * LL + colX) = pack2h(h0, h1);
            *(uint32_t*)(EH + (size_t)rowB * LL + colX) = pack2h(h2, h3);
        }
        sA += __shfl_xor_sync(0xffffffffu, sA, 1);
        sA += __shfl_xor_sync(0xffffffffu, sA, 2);
        sB += __shfl_xor_sync(0xffffffffu, sB, 1);
        sB += __shfl_xor_sync(0xffffffffu, sB, 2);
        if (t == 0) { rs[lrA][warp_n] = sA; rs[lrB][warp_n] = sB; }
    }
    __syncthreads();

    if (tid < 128)
        g_partial[((size_t)bh * LL + row0 + tid) * 8 + nt] =
            rs[tid][0] + rs[tid][1] + rs[tid][2] + rs[tid][3];
}

// ===========================================================================
// Kernel 2 (HMMA): P = E'*rinv -> series (single write) and O = P @ V.
// Reads fp16 E' from scratch. 512 CTAs big-tile-first; s-chunks of 64;
// double-buffered fp16 hi/lo staging; 1 sync/chunk.
// ===========================================================================
#define AV_BUF0   1024
#define AV_BUFSZ  49152
#define AV_PHO    0
#define AV_PLO    16384
#define AV_VHO    32768
#define AV_VLO    40960
#define AV_SMEM   (1024 + 2 * 49152)   // 99328 B

__device__ __forceinline__ void av_stage(
    const uint4* eh, const float4* vv, float* __restrict__ S,
    const float* __restrict__ rinv, char* __restrict__ buf,
    int row0, int s0, int tid) {
    char* Ph = buf + AV_PHO;
    char* Pl = buf + AV_PLO;
    char* Vh = buf + AV_VHO;
    char* Vl = buf + AV_VLO;
    #pragma unroll
    for (int it = 0; it < 4; it++) {
        int flat = it * 256 + tid;      // 1024 uint4 = 128 rows x 8
        int c8 = flat & 7;              // 8 halves per uint4
        int m  = flat >> 3;
        float r = rinv[m];
        uint4 u = eh[it];
        __half2 a0 = *(__half2*)&u.x, a1 = *(__half2*)&u.y;
        __half2 a2 = *(__half2*)&u.z, a3 = *(__half2*)&u.w;
        float2 f0 = __half22float2(a0), f1 = __half22float2(a1);
        float2 f2 = __half22float2(a2), f3 = __half22float2(a3);
        f0.x *= r; f0.y *= r; f1.x *= r; f1.y *= r;
        f2.x *= r; f2.y *= r; f3.x *= r; f3.y *= r;
        float* sd = S + (size_t)(row0 + m) * LL + s0 + c8 * 8;
        *(float4*)sd       = make_float4(f0.x, f0.y, f1.x, f1.y);
        *(float4*)(sd + 4) = make_float4(f2.x, f2.y, f3.x, f3.y);
        __half2 p0 = __float22half2_rn(f0), p1 = __float22half2_rn(f1);
        __half2 p2 = __float22half2_rn(f2), p3 = __float22half2_rn(f3);
        uint32_t so = sw128((uint32_t)(m * 128 + c8 * 16));
        *(uint4*)(Ph + so) = make_uint4(
            *(uint32_t*)&p0, *(uint32_t*)&p1, *(uint32_t*)&p2, *(uint32_t*)&p3);
        __half2 l0 = __floats2half2_rn(f0.x - __low2float(p0), f0.y - __high2float(p0));
        __half2 l1 = __floats2half2_rn(f1.x - __low2float(p1), f1.y - __high2float(p1));
        __half2 l2 = __floats2half2_rn(f2.x - __low2float(p2), f2.y - __high2float(p2));
        __half2 l3 = __floats2half2_rn(f3.x - __low2float(p3), f3.y - __high2float(p3));
        *(uint4*)(Pl + so) = make_uint4(
            *(uint32_t*)&l0, *(uint32_t*)&l1, *(uint32_t*)&l2, *(uint32_t*)&l3);
    }
    #pragma unroll
    for (int it = 0; it < 4; it++) {
        int flat = it * 256 + tid;      // 1024 float4 = 64 x 16
        int c4 = flat & 15;
        int s  = flat >> 4;
        float4 w = vv[it];
        uint32_t so = sw128((uint32_t)(s * 128 + c4 * 8));
        half vx = __float2half_rn(w.x), vy = __float2half_rn(w.y);
        half vz = __float2half_rn(w.z), vw = __float2half_rn(w.w);
        *(uint2*)(Vh + so) = make_uint2(pack2h(vx, vy), pack2h(vz, vw));
        *(uint2*)(Vl + so) = make_uint2(
            pack2h(__float2half_rn(w.x - __half2float(vx)),
                   __float2half_rn(w.y - __half2float(vy))),
            pack2h(__float2half_rn(w.z - __half2float(vz)),
                   __float2half_rn(w.w - __half2float(vw))));
    }
}

__global__ __launch_bounds__(256, 2)
void k_av(const float* __restrict__ V, float* __restrict__ series,
          float* __restrict__ outV) {
    extern __shared__ __align__(1024) char avsm[];
    const int bx = blockIdx.x;
    const int mt = 7 - (bx >> 6);       // big tiles first
    const int bh = bx & 63;
    const int b  = bh >> 3;
    const int h  = bh & 7;
    const int tid = threadIdx.x;
    const int wid = tid >> 5, lane = tid & 31;
    const int warp_m = wid & 3, warp_n = wid >> 2;
    const int m0 = warp_m * 32, n0 = warp_n * 32;
    const int g = lane >> 2, t = lane & 3;

    float* rinv = (float*)avsm;
    const uint32_t smb = smem_u32(avsm);

    float* S = series + (size_t)bh * LL * LL;
    const __half* EH = g_eh + (size_t)bh * LL * LL;
    const float* Vg = V + (size_t)b * LL * (HH * DD) + h * DD;

    const int a_row = (lane & 7) + ((lane >> 3) & 1) * 8;
    const int a_c16 = (lane >> 4) & 1;
    const int v_row = (lane & 7) + ((lane >> 3) & 1) * 8;
    const int v_n8  = (lane >> 4) & 1;

    uint32_t offA[2], offVb[2];
    #pragma unroll
    for (int im = 0; im < 2; im++)
        offA[im] = (uint32_t)((m0 + im * 16 + a_row) * 128 + a_c16 * 16);
    #pragma unroll
    for (int in16 = 0; in16 < 2; in16++)
        offVb[in16] = (uint32_t)(v_row * 128 + n0 * 2 + in16 * 32 + v_n8 * 16);

    const int row0 = mt * 128;
    const int nchunks = 2 * (mt + 1);   // s-chunks of 64

    if (tid < 128) {
        float s = 0.f;
        for (int nt = 0; nt <= mt; nt++)
            s += g_partial[((size_t)bh * LL + row0 + tid) * 8 + nt];
        rinv[tid] = 1.0f / s;
    }
    __syncthreads();

    float c[2][4][4];
    #pragma unroll
    for (int im = 0; im < 2; im++)
        #pragma unroll
        for (int in = 0; in < 4; in++)
            #pragma unroll
            for (int q = 0; q < 4; q++) c[im][in][q] = 0.f;

    uint4 eh[4];
    float4 vv[4];

    {   // prolog: chunk 0 -> buffer 0
        const int s0 = mt * 128;
        #pragma unroll
        for (int it = 0; it < 4; it++) {
            int flat = it * 256 + tid;
            int c8 = flat & 7;
            int m  = flat >> 3;
            eh[it] = *(const uint4*)(EH + (size_t)(row0 + m) * LL + s0 + c8 * 8);
        }
        #pragma unroll
        for (int it = 0; it < 4; it++) {
            int flat = it * 256 + tid;
            int c4 = flat & 15;
            int s  = flat >> 4;
            vv[it] = *(const float4*)(Vg + (size_t)(s0 + s) * 512 + c4 * 4);
        }
        av_stage(eh, vv, S, rinv, avsm + AV_BUF0, row0, s0, tid);
    }
    __syncthreads();

    for (int cc = 0; cc < nchunks; cc++) {
        const int buf = cc & 1;
        const bool more = (cc + 1 < nchunks);
        int s0n = 0;
        if (more) {
            const int cn = cc + 1;
            const int ntn = mt - (cn >> 1);
            s0n = ntn * 128 + (cn & 1) * 64;
            #pragma unroll
            for (int it = 0; it < 4; it++) {
                int flat = it * 256 + tid;
                int c8 = flat & 7;
                int m  = flat >> 3;
                eh[it] = *(const uint4*)(EH + (size_t)(row0 + m) * LL + s0n + c8 * 8);
            }
            #pragma unroll
            for (int it = 0; it < 4; it++) {
                int flat = it * 256 + tid;
                int c4 = flat & 15;
                int s  = flat >> 4;
                vv[it] = *(const float4*)(Vg + (size_t)(s0n + s) * 512 + c4 * 4);
            }
        }

        // ---- compute current buffer ----
        {
            const uint32_t base = smb + AV_BUF0 + buf * AV_BUFSZ;
            #pragma unroll
            for (int ks = 0; ks < 4; ks++) {
                const uint32_t ko = ks * 32;        // A k-byte offset
                const uint32_t vr = ks * 2048;      // V row offset (16 rows)
                U4 A[2], Bh[2], Bl[2];
                #pragma unroll
                for (int in16 = 0; in16 < 2; in16++)
                    Bh[in16] = ldmx4t(base + AV_VHO + sw128(offVb[in16] + vr));
                #pragma unroll
                for (int im = 0; im < 2; im++)
                    A[im] = ldmx4(base + AV_PHO + sw128(offA[im] + ko));
                #pragma unroll
                for (int im = 0; im < 2; im++) {
                    mma16816(c[im][0], A[im], Bh[0].x, Bh[0].y);
                    mma16816(c[im][1], A[im], Bh[0].z, Bh[0].w);
                    mma16816(c[im][2], A[im], Bh[1].x, Bh[1].y);
                    mma16816(c[im][3], A[im], Bh[1].z, Bh[1].w);
                }
                #pragma unroll
                for (int in16 = 0; in16 < 2; in16++)
                    Bl[in16] = ldmx4t(base + AV_VLO + sw128(offVb[in16] + vr));
                #pragma unroll
                for (int im = 0; im < 2; im++) {
                    mma16816(c[im][0], A[im], Bl[0].x, Bl[0].y);
                    mma16816(c[im][1], A[im], Bl[0].z, Bl[0].w);
                    mma16816(c[im][2], A[im], Bl[1].x, Bl[1].y);
                    mma16816(c[im][3], A[im], Bl[1].z, Bl[1].w);
                }
                #pragma unroll
                for (int im = 0; im < 2; im++)
                    A[im] = ldmx4(base + AV_PLO + sw128(offA[im] + ko));
                #pragma unroll
                for (int im = 0; im < 2; im++) {
                    mma16816(c[im][0], A[im], Bh[0].x, Bh[0].y);
                    mma16816(c[im][1], A[im], Bh[0].z, Bh[0].w);
                    mma16816(c[im][2], A[im], Bh[1].x, Bh[1].y);
                    mma16816(c[im][3], A[im], Bh[1].z, Bh[1].w);
                }
            }
        }

        if (more)
            av_stage(eh, vv, S, rinv, avsm + AV_BUF0 + (buf ^ 1) * AV_BUFSZ,
                     row0, s0n, tid);
        __syncthreads();
    }

    // ---- output O tile ----
    float* Og = outV + (size_t)b * LL * (HH * DD) + h * DD;
    #pragma unroll
    for (int im = 0; im < 2; im++) {
        const int rowA = row0 + m0 + im * 16 + g;
        const int rowB = rowA + 8;
        #pragma unroll
        for (int in = 0; in < 4; in++) {
            const int col = n0 + in * 8 + 2 * t;
            *(float2*)(Og + (size_t)rowA * 512 + col) =
                make_float2(c[im][in][0], c[im][in][1]);
            *(float2*)(Og + (size_t)rowB * 512 + col) =
                make_float2(c[im][in][2], c[im][in][3]);
        }
    }
}

// ---------------------------------------------------------------------------
extern "C" void kernel_launch(void* const* d_in, const int* in_sizes, int n_in,
                              void* d_out, int out_size) {
    (void)in_sizes; (void)n_in; (void)out_size;
    const float* Q   = (const float*)d_in[0];
    const float* K   = (const float*)d_in[1];
    const float* V   = (const float*)d_in[2];
    const float* sig = (const float*)d_in[3];
    float* out    = (float*)d_out;
    float* outV   = out;                 // (B,L,H,D)
    float* series = out + OFF_SERIES;    // (B,H,L,S)
    float* prior  = out + OFF_PRIOR;     // (B,L,S)

    cudaFuncSetAttribute(k_scores, cudaFuncAttributeMaxDynamicSharedMemorySize,
                         KS_SMEM);
    cudaFuncSetAttribute(k_av, cudaFuncAttributeMaxDynamicSharedMemorySize,
                         AV_SMEM);

    k_scores<<<dim3(8, 8, 4 + Bb * HH), 256, KS_SMEM>>>(Q, K, series, sig, prior);
    k_av    <<<dim3(512, 1),           256, AV_SMEM>>>(V, series, outV);
}

// round 17
// speedup vs baseline: 1.3191x; 1.0457x over previous
#include <cuda_runtime.h>
#include <cuda_bf16.h>
#include <cuda_fp16.h>
#include <cstdint>

// Problem constants
#define Bb 8
#define LL 1024
#define HH 8
#define EE 64
#define DD 64
#define SCALE 0.125f   // 1/sqrt(64)

// Output layout (concatenated flattened tuple):
//   V:      (B,L,H,D)   at 0              size 4,194,304
//   series: (B,H,L,S)   at 4,194,304      size 67,108,864
//   prior:  (B,L,S)     at 71,303,168     size 8,388,608
#define OFF_SERIES 4194304
#define OFF_PRIOR  71303168

// Scratch: per-(b,h,row,ntile) partial row sums of rounded exp scores.
__device__ float g_partial[Bb * HH * LL * 8];          // 2 MB
// Scratch: causal E tiles in fp16 (upper triangle never touched).
__device__ __half g_eh[(size_t)Bb * HH * LL * LL];     // 128 MB

// ---------------- warp-MMA helpers (sm_80-era PTX, sm_103-portable) --------
struct U4 { uint32_t x, y, z, w; };

__device__ __forceinline__ U4 ldmx4(uint32_t a) {
    U4 r;
    asm volatile("ldmatrix.sync.aligned.m8n8.x4.shared.b16 {%0,%1,%2,%3}, [%4];"
                 : "=r"(r.x), "=r"(r.y), "=r"(r.z), "=r"(r.w) : "r"(a));
    return r;
}
__device__ __forceinline__ U4 ldmx4t(uint32_t a) {
    U4 r;
    asm volatile("ldmatrix.sync.aligned.m8n8.x4.trans.shared.b16 {%0,%1,%2,%3}, [%4];"
                 : "=r"(r.x), "=r"(r.y), "=r"(r.z), "=r"(r.w) : "r"(a));
    return r;
}
__device__ __forceinline__ void mma16816(float* c, const U4& a,
                                         uint32_t b0, uint32_t b1) {
    asm volatile("mma.sync.aligned.m16n8k16.row.col.f32.f16.f16.f32 "
                 "{%0,%1,%2,%3}, {%4,%5,%6,%7}, {%8,%9}, {%0,%1,%2,%3};"
                 : "+f"(c[0]), "+f"(c[1]), "+f"(c[2]), "+f"(c[3])
                 : "r"(a.x), "r"(a.y), "r"(a.z), "r"(a.w), "r"(b0), "r"(b1));
}
__device__ __forceinline__ uint32_t pack2h(half a, half b) {
    return (uint32_t)__half_as_ushort(a) | ((uint32_t)__half_as_ushort(b) << 16);
}
__device__ __forceinline__ uint32_t smem_u32(const void* p) {
    uint32_t a;
    asm("{ .reg .u64 t; cvta.to.shared.u64 t, %1; cvt.u32.u64 %0, t; }"
        : "=r"(a) : "l"(p));
    return a;
}
// SW128 swizzle (Swizzle<3,4,3>) on byte offsets within a 128B-row tile
__device__ __forceinline__ uint32_t sw128(uint32_t off) {
    return off ^ ((off >> 3) & 0x70);
}

// ===========================================================================
// Kernel 1 (HMMA + fused prior): grid (8, 8, 4+64).
//   z < 4  : prior-association blocks (long-running; scheduled FIRST)
//   z >= 4 : causal tile: E' = fp16(exp(scale*QK^T)) -> g_eh; rowsums of E'.
//            Upper tiles: zero-fill series.  (R16, unchanged)
// ===========================================================================
#define SMQ_H 0
#define SMQ_L 16384
#define SMK_H 32768
#define SMK_L 49152
#define KS_SMEM 65536

__global__ __launch_bounds__(256, 2)
void k_scores(const float* __restrict__ Q, const float* __restrict__ K,
              float* __restrict__ series,
              const float* __restrict__ sigma, float* __restrict__ prior) {
    extern __shared__ __align__(1024) char dsm[];
    const int tid = threadIdx.x;

    // ---------------- prior path (z = 0..3) ----------------
    if (blockIdx.z < 4) {
        const int flat = blockIdx.z * 64 + blockIdx.y * 8 + blockIdx.x;
        const int i0 = (flat >> 3) * 32;
        const int b  = flat & 7;
        float* rl  = (float*)dsm;              // [8][1024]
        float* red = (float*)(dsm + 32768);    // [8]

        for (int idx = tid; idx < 8 * 1024; idx += 256) {
            int hh = idx >> 10;
            int s  = idx & 1023;
            rl[hh * 1024 + s] = -1.0f / sigma[((size_t)b * 8 + hh) * 1024 + s];
        }
        __syncthreads();

        const int lane = tid & 31, wd = tid >> 5;
        for (int ii = 0; ii < 32; ii++) {
            const int i = i0 + ii;
            float p[4];
            float sum = 0.f;
            #pragma unroll
            for (int j = 0; j < 4; j++) {
                const int s = tid + j * 256;
                const float d = (float)((i > s) ? (i - s) : (s - i));
                float a = 0.f;
                #pragma unroll
                for (int hh = 0; hh < 8; hh++)
                    a += __expf(d * rl[hh * 1024 + s]);
                p[j] = a;
                sum += a;
            }
            #pragma unroll
            for (int off = 16; off; off >>= 1)
                sum += __shfl_xor_sync(0xffffffffu, sum, off);
            if (lane == 0) red[wd] = sum;
            __syncthreads();
            float tot = 0.f;
            #pragma unroll
            for (int w = 0; w < 8; w++) tot += red[w];
            const float inv = 1.0f / tot;
            float* dst = prior + (size_t)(b * 1024 + i) * 1024;
            #pragma unroll
            for (int j = 0; j < 4; j++)
                dst[tid + j * 256] = p[j] * inv;
            __syncthreads();
        }
        return;
    }

    // ---------------- scores path (z = 4..67) ----------------
    const int nt = blockIdx.x;
    const int mt = blockIdx.y;
    const int bh = blockIdx.z - 4;      // b*8 + h
    const int b  = bh >> 3;
    const int h  = bh & 7;

    float* S = series + (size_t)bh * LL * LL;
    const int row0 = mt * 128, col0 = nt * 128;

    if (nt > mt) {
        const float4 z = make_float4(0.f, 0.f, 0.f, 0.f);
        #pragma unroll
        for (int i = 0; i < 16; i++) {
            int flat = i * 256 + tid;
            int r = flat >> 5;
            int c = (flat & 31) << 2;
            *(float4*)(S + (size_t)(row0 + r) * LL + col0 + c) = z;
        }
        return;
    }

    __shared__ float rs[128][4];   // per-(row, warp_n) partial sums

    const uint32_t smb = smem_u32(dsm);
    const int wid = tid >> 5, lane = tid & 31;
    const int warp_m = wid & 1, warp_n = wid >> 1;
    const int m0 = warp_m * 64, n0w = warp_n * 32;
    const int g = lane >> 2, t = lane & 3;

    const float* Qg = Q + (size_t)b * LL * (HH * EE) + h * EE;  // + l*512 + e
    const float* Kg = K + (size_t)b * LL * (HH * EE) + h * EE;
    #pragma unroll
    for (int it = 0; it < 8; it++) {
        int flat = it * 256 + tid;      // 2048 float4 per matrix
        int c4 = flat & 15;
        int r  = flat >> 4;
        uint32_t so = sw128((uint32_t)(r * 128 + c4 * 8));

        float4 v = *(const float4*)(Qg + (size_t)(row0 + r) * 512 + c4 * 4);
        half hx = __float2half_rn(v.x), hy = __float2half_rn(v.y);
        half hz = __float2half_rn(v.z), hw = __float2half_rn(v.w);
        *(uint2*)(dsm + SMQ_H + so) = make_uint2(pack2h(hx, hy), pack2h(hz, hw));
        *(uint2*)(dsm + SMQ_L + so) = make_uint2(
            pack2h(__float2half_rn(v.x - __half2float(hx)),
                   __float2half_rn(v.y - __half2float(hy))),
            pack2h(__float2half_rn(v.z - __half2float(hz)),
                   __float2half_rn(v.w - __half2float(hw))));

        float4 w = *(const float4*)(Kg + (size_t)(col0 + r) * 512 + c4 * 4);
        half kx = __float2half_rn(w.x), ky = __float2half_rn(w.y);
        half kz = __float2half_rn(w.z), kw = __float2half_rn(w.w);
        *(uint2*)(dsm + SMK_H + so) = make_uint2(pack2h(kx, ky), pack2h(kz, kw));
        *(uint2*)(dsm + SMK_L + so) = make_uint2(
            pack2h(__float2half_rn(w.x - __half2float(kx)),
                   __float2half_rn(w.y - __half2float(ky))),
            pack2h(__float2half_rn(w.z - __half2float(kz)),
                   __float2half_rn(w.w - __half2float(kw))));
    }
    __syncthreads();

    const int a_row = (lane & 7) + ((lane >> 3) & 1) * 8;
    const int a_c16 = (lane >> 4) & 1;
    const int b_row = (lane & 7) + ((lane >> 4) & 1) * 8;
    const int b_c16 = (lane >> 3) & 1;

    uint32_t offA[4], offB[2];
    #pragma unroll
    for (int im = 0; im < 4; im++)
        offA[im] = (uint32_t)((m0 + im * 16 + a_row) * 128 + a_c16 * 16);
    #pragma unroll
    for (int hb = 0; hb < 2; hb++)
        offB[hb] = (uint32_t)((n0w + hb * 16 + b_row) * 128 + b_c16 * 16);

    float c[4][4][4];
    #pragma unroll
    for (int im = 0; im < 4; im++)
        #pragma unroll
        for (int in = 0; in < 4; in++)
            #pragma unroll
            for (int q = 0; q < 4; q++) c[im][in][q] = 0.f;

    #pragma unroll
    for (int ks = 0; ks < 4; ks++) {
        const uint32_t ko = ks * 32;
        U4 A[4], Bh[2], Bl[2];
        #pragma unroll
        for (int hb = 0; hb < 2; hb++)
            Bh[hb] = ldmx4(smb + SMK_H + sw128(offB[hb] + ko));
        #pragma unroll
        for (int im = 0; im < 4; im++)
            A[im] = ldmx4(smb + SMQ_H + sw128(offA[im] + ko));
        #pragma unroll
        for (int im = 0; im < 4; im++) {
            mma16816(c[im][0], A[im], Bh[0].x, Bh[0].y);
            mma16816(c[im][1], A[im], Bh[0].z, Bh[0].w);
            mma16816(c[im][2], A[im], Bh[1].x, Bh[1].y);
            mma16816(c[im][3], A[im], Bh[1].z, Bh[1].w);
        }
        #pragma unroll
        for (int hb = 0; hb < 2; hb++)
            Bl[hb] = ldmx4(smb + SMK_L + sw128(offB[hb] + ko));
        #pragma unroll
        for (int im = 0; im < 4; im++) {
            mma16816(c[im][0], A[im], Bl[0].x, Bl[0].y);
            mma16816(c[im][1], A[im], Bl[0].z, Bl[0].w);
            mma16816(c[im][2], A[im], Bl[1].x, Bl[1].y);
            mma16816(c[im][3], A[im], Bl[1].z, Bl[1].w);
        }
        #pragma unroll
        for (int im = 0; im < 4; im++)
            A[im] = ldmx4(smb + SMQ_L + sw128(offA[im] + ko));
        #pragma unroll
        for (int im = 0; im < 4; im++) {
            mma16816(c[im][0], A[im], Bh[0].x, Bh[0].y);
            mma16816(c[im][1], A[im], Bh[0].z, Bh[0].w);
            mma16816(c[im][2], A[im], Bh[1].x, Bh[1].y);
            mma16816(c[im][3], A[im], Bh[1].z, Bh[1].w);
        }
    }

    // ---- epilogue: mask + exp; round to fp16; rowsums of ROUNDED values;
    //      store fp16 E' to scratch (series untouched for causal tiles) ----
    __half* EH = g_eh + (size_t)bh * LL * LL;
    #pragma unroll
    for (int im = 0; im < 4; im++) {
        const int lrA = m0 + im * 16 + g;
        const int lrB = lrA + 8;
        const int rowA = row0 + lrA, rowB = row0 + lrB;
        float sA = 0.f, sB = 0.f;
        #pragma unroll
        for (int in = 0; in < 4; in++) {
            const int cb = n0w + in * 8 + 2 * t;
            const int colX = col0 + cb, colY = colX + 1;
            float e0 = (colX <= rowA) ? __expf(SCALE * c[im][in][0]) : 0.f;
            float e1 = (colY <= rowA) ? __expf(SCALE * c[im][in][1]) : 0.f;
            float e2 = (colX <= rowB) ? __expf(SCALE * c[im][in][2]) : 0.f;
            float e3 = (colY <= rowB) ? __expf(SCALE * c[im][in][3]) : 0.f;
            half h0 = __float2half_rn(e0), h1 = __float2half_rn(e1);
            half h2 = __float2half_rn(e2), h3 = __float2half_rn(e3);
            sA += __half2float(h0) + __half2float(h1);
            sB += __half2float(h2) + __half2float(h3);
            *(uint32_t*)(EH + (size_t)rowA * LL + colX) = pack2h(h0, h1);
            *(uint32_t*)(EH + (size_t)rowB * LL + colX) = pack2h(h2, h3);
        }
        sA += __shfl_xor_sync(0xffffffffu, sA, 1);
        sA += __shfl_xor_sync(0xffffffffu, sA, 2);
        sB += __shfl_xor_sync(0xffffffffu, sB, 1);
        sB += __shfl_xor_sync(0xffffffffu, sB, 2);
        if (t == 0) { rs[lrA][warp_n] = sA; rs[lrB][warp_n] = sB; }
    }
    __syncthreads();

    if (tid < 128)
        g_partial[((size_t)bh * LL + row0 + tid) * 8 + nt] =
            rs[tid][0] + rs[tid][1] + rs[tid][2] + rs[tid][3];
}

// ===========================================================================
// Kernel 2 (HMMA): P = E'*rinv -> series (single write); O = rinv*(E' @ V).
// A-operand of the MMA is RAW E' (exact in fp16, no lo term!); rinv applied
// to O registers at the end. 2 MMA term-groups per ks (E'*Vh + E'*Vl).
// ===========================================================================
#define AV_BUF0   1024
#define AV_BUFSZ  32768
#define AV_EHO    0          // raw E' chunk: 128x64 fp16 = 16KB
#define AV_VHO    16384      // V hi: 64x64 fp16 = 8KB
#define AV_VLO    24576      // V lo: 8KB
#define AV_SMEM   (1024 + 2 * 32768)   // 66560 B

__device__ __forceinline__ void av_stage(
    const uint4* eh, const float4* vv, float* __restrict__ S,
    const float* __restrict__ rinv, char* __restrict__ buf,
    int row0, int s0, int tid) {
    char* Eh = buf + AV_EHO;
    char* Vh = buf + AV_VHO;
    char* Vl = buf + AV_VLO;
    #pragma unroll
    for (int it = 0; it < 4; it++) {
        int flat = it * 256 + tid;      // 1024 uint4 = 128 rows x 8
        int c8 = flat & 7;              // 8 halves per uint4
        int m  = flat >> 3;
        uint4 u = eh[it];
        // raw E' copy into smem (A-operand for MMA, zero conversion)
        *(uint4*)(Eh + sw128((uint32_t)(m * 128 + c8 * 16))) = u;
        // decode + scale -> P fp32 to series (mandatory output)
        float r = rinv[m];
        __half2 a0 = *(__half2*)&u.x, a1 = *(__half2*)&u.y;
        __half2 a2 = *(__half2*)&u.z, a3 = *(__half2*)&u.w;
        float2 f0 = __half22float2(a0), f1 = __half22float2(a1);
        float2 f2 = __half22float2(a2), f3 = __half22float2(a3);
        float* sd = S + (size_t)(row0 + m) * LL + s0 + c8 * 8;
        *(float4*)sd       = make_float4(f0.x * r, f0.y * r, f1.x * r, f1.y * r);
        *(float4*)(sd + 4) = make_float4(f2.x * r, f2.y * r, f3.x * r, f3.y * r);
    }
    #pragma unroll
    for (int it = 0; it < 4; it++) {
        int flat = it * 256 + tid;      // 1024 float4 = 64 x 16
        int c4 = flat & 15;
        int s  = flat >> 4;
        float4 w = vv[it];
        uint32_t so = sw128((uint32_t)(s * 128 + c4 * 8));
        half vx = __float2half_rn(w.x), vy = __float2half_rn(w.y);
        half vz = __float2half_rn(w.z), vw = __float2half_rn(w.w);
        *(uint2*)(Vh + so) = make_uint2(pack2h(vx, vy), pack2h(vz, vw));
        *(uint2*)(Vl + so) = make_uint2(
            pack2h(__float2half_rn(w.x - __half2float(vx)),
                   __float2half_rn(w.y - __half2float(vy))),
            pack2h(__float2half_rn(w.z - __half2float(vz)),
                   __float2half_rn(w.w - __half2float(vw))));
    }
}

__global__ __launch_bounds__(256, 2)
void k_av(const float* __restrict__ V, float* __restrict__ series,
          float* __restrict__ outV) {
    extern __shared__ __align__(1024) char avsm[];
    const int bx = blockIdx.x;
    const int mt = 7 - (bx >> 6);       // big tiles first
    const int bh = bx & 63;
    const int b  = bh >> 3;
    const int h  = bh & 7;
    const int tid = threadIdx.x;
    const int wid = tid >> 5, lane = tid & 31;
    const int warp_m = wid & 3, warp_n = wid >> 2;
    const int m0 = warp_m * 32, n0 = warp_n * 32;
    const int g = lane >> 2, t = lane & 3;

    float* rinv = (float*)avsm;
    const uint32_t smb = smem_u32(avsm);

    float* S = series + (size_t)bh * LL * LL;
    const __half* EH = g_eh + (size_t)bh * LL * LL;
    const float* Vg = V + (size_t)b * LL * (HH * DD) + h * DD;

    const int a_row = (lane & 7) + ((lane >> 3) & 1) * 8;
    const int a_c16 = (lane >> 4) & 1;
    const int v_row = (lane & 7) + ((lane >> 3) & 1) * 8;
    const int v_n8  = (lane >> 4) & 1;

    uint32_t offA[2], offVb[2];
    #pragma unroll
    for (int im = 0; im < 2; im++)
        offA[im] = (uint32_t)((m0 + im * 16 + a_row) * 128 + a_c16 * 16);
    #pragma unroll
    for (int in16 = 0; in16 < 2; in16++)
        offVb[in16] = (uint32_t)(v_row * 128 + n0 * 2 + in16 * 32 + v_n8 * 16);

    const int row0 = mt * 128;
    const int nchunks = 2 * (mt + 1);   // s-chunks of 64

    if (tid < 128) {
        float s = 0.f;
        for (int nt = 0; nt <= mt; nt++)
            s += g_partial[((size_t)bh * LL + row0 + tid) * 8 + nt];
        rinv[tid] = 1.0f / s;
    }
    __syncthreads();

    float c[2][4][4];
    #pragma unroll
    for (int im = 0; im < 2; im++)
        #pragma unroll
        for (int in = 0; in < 4; in++)
            #pragma unroll
            for (int q = 0; q < 4; q++) c[im][in][q] = 0.f;

    uint4 eh[4];
    float4 vv[4];

    {   // prolog: chunk 0 -> buffer 0
        const int s0 = mt * 128;
        #pragma unroll
        for (int it = 0; it < 4; it++) {
            int flat = it * 256 + tid;
            int c8 = flat & 7;
            int m  = flat >> 3;
            eh[it] = *(const uint4*)(EH + (size_t)(row0 + m) * LL + s0 + c8 * 8);
        }
        #pragma unroll
        for (int it = 0; it < 4; it++) {
            int flat = it * 256 + tid;
            int c4 = flat & 15;
            int s  = flat >> 4;
            vv[it] = *(const float4*)(Vg + (size_t)(s0 + s) * 512 + c4 * 4);
        }
        av_stage(eh, vv, S, rinv, avsm + AV_BUF0, row0, s0, tid);
    }
    __syncthreads();

    for (int cc = 0; cc < nchunks; cc++) {
        const int buf = cc & 1;
        const bool more = (cc + 1 < nchunks);
        int s0n = 0;
        if (more) {
            const int cn = cc + 1;
            const int ntn = mt - (cn >> 1);
            s0n = ntn * 128 + (cn & 1) * 64;
            #pragma unroll
            for (int it = 0; it < 4; it++) {
                int flat = it * 256 + tid;
                int c8 = flat & 7;
                int m  = flat >> 3;
                eh[it] = *(const uint4*)(EH + (size_t)(row0 + m) * LL + s0n + c8 * 8);
            }
            #pragma unroll
            for (int it = 0; it < 4; it++) {
                int flat = it * 256 + tid;
                int c4 = flat & 15;
                int s  = flat >> 4;
                vv[it] = *(const float4*)(Vg + (size_t)(s0n + s) * 512 + c4 * 4);
            }
        }

        // ---- compute current buffer: O += E' * (Vh + Vl) ----
        {
            const uint32_t base = smb + AV_BUF0 + buf * AV_BUFSZ;
            #pragma unroll
            for (int ks = 0; ks < 4; ks++) {
                const uint32_t ko = ks * 32;        // A k-byte offset
                const uint32_t vr = ks * 2048;      // V row offset (16 rows)
                U4 A[2], Bh[2], Bl[2];
                #pragma unroll
                for (int in16 = 0; in16 < 2; in16++)
                    Bh[in16] = ldmx4t(base + AV_VHO + sw128(offVb[in16] + vr));
                #pragma unroll
                for (int im = 0; im < 2; im++)
                    A[im] = ldmx4(base + AV_EHO + sw128(offA[im] + ko));
                #pragma unroll
                for (int im = 0; im < 2; im++) {
                    mma16816(c[im][0], A[im], Bh[0].x, Bh[0].y);
                    mma16816(c[im][1], A[im], Bh[0].z, Bh[0].w);
                    mma16816(c[im][2], A[im], Bh[1].x, Bh[1].y);
                    mma16816(c[im][3], A[im], Bh[1].z, Bh[1].w);
                }
                #pragma unroll
                for (int in16 = 0; in16 < 2; in16++)
                    Bl[in16] = ldmx4t(base + AV_VLO + sw128(offVb[in16] + vr));
                #pragma unroll
                for (int im = 0; im < 2; im++) {
                    mma16816(c[im][0], A[im], Bl[0].x, Bl[0].y);
                    mma16816(c[im][1], A[im], Bl[0].z, Bl[0].w);
                    mma16816(c[im][2], A[im], Bl[1].x, Bl[1].y);
                    mma16816(c[im][3], A[im], Bl[1].z, Bl[1].w);
                }
            }
        }

        if (more)
            av_stage(eh, vv, S, rinv, avsm + AV_BUF0 + (buf ^ 1) * AV_BUFSZ,
                     row0, s0n, tid);
        __syncthreads();
    }

    // ---- output O tile (apply rinv per row in fp32) ----
    float* Og = outV + (size_t)b * LL * (HH * DD) + h * DD;
    #pragma unroll
    for (int im = 0; im < 2; im++) {
        const int lrA = m0 + im * 16 + g;
        const int rowA = row0 + lrA;
        const int rowB = rowA + 8;
        const float rA = rinv[lrA];
        const float rB = rinv[lrA + 8];
        #pragma unroll
        for (int in = 0; in < 4; in++) {
            const int col = n0 + in * 8 + 2 * t;
            *(float2*)(Og + (size_t)rowA * 512 + col) =
                make_float2(c[im][in][0] * rA, c[im][in][1] * rA);
            *(float2*)(Og + (size_t)rowB * 512 + col) =
                make_float2(c[im][in][2] * rB, c[im][in][3] * rB);
        }
    }
}

// ---------------------------------------------------------------------------
extern "C" void kernel_launch(void* const* d_in, const int* in_sizes, int n_in,
                              void* d_out, int out_size) {
    (void)in_sizes; (void)n_in; (void)out_size;
    const float* Q   = (const float*)d_in[0];
    const float* K   = (const float*)d_in[1];
    const float* V   = (const float*)d_in[2];
    const float* sig = (const float*)d_in[3];
    float* out    = (float*)d_out;
    float* outV   = out;                 // (B,L,H,D)
    float* series = out + OFF_SERIES;    // (B,H,L,S)
    float* prior  = out + OFF_PRIOR;     // (B,L,S)

    cudaFuncSetAttribute(k_scores, cudaFuncAttributeMaxDynamicSharedMemorySize,
                         KS_SMEM);
    cudaFuncSetAttribute(k_av, cudaFuncAttributeMaxDynamicSharedMemorySize,
                         AV_SMEM);

    k_scores<<<dim3(8, 8, 4 + Bb * HH), 256, KS_SMEM>>>(Q, K, series, sig, prior);
    k_av    <<<dim3(512, 1),           256, AV_SMEM>>>(V, series, outV);
}